// round 2
// baseline (speedup 1.0000x reference)
#include <cuda_runtime.h>
#include <math.h>
#include <stdint.h>
#include <stddef.h>

// Problem dims (fixed)
#define BB 4
#define SS 2048
#define DD 1024
#define HH 16
#define HD 64
#define FF 4096

static const size_t NX = (size_t)BB * SS * DD;        // 8388608

// Scratch (device globals; allocation APIs are forbidden)
__device__ float g_xq [8388608];
__device__ float g_q  [8388608];
__device__ float g_k  [8388608];
__device__ float g_v  [8388608];
__device__ float g_ctx[8388608];
__device__ float g_o  [8388608];
__device__ float g_h  [8388608];
__device__ float g_f  [33554432];
__device__ float g_f2 [8388608];
__device__ unsigned int g_amax[2];

// ---------------------------------------------------------------------------
// qdq: quantize_per_tensor(zp=64, quint8) + dequantize, matching
//   q = clip(round(x/scale)+64, 0, 255); (q-64)*scale
// with IEEE division and round-half-to-even to match the JAX fp32 reference.
__device__ __forceinline__ float qdqf(float x, float s) {
    float r = rintf(__fdiv_rn(x, s));
    r = fminf(fmaxf(r + 64.0f, 0.0f), 255.0f);
    return (r - 64.0f) * s;
}

// ---------------------------------------------------------------------------
__global__ void __launch_bounds__(32)
init_amax_kernel() {
    if (threadIdx.x < 2) g_amax[threadIdx.x] = 0u;
}

__global__ void __launch_bounds__(256)
absmax_kernel(const float* __restrict__ X, size_t n4, unsigned int* __restrict__ out) {
    __shared__ float red[8];
    int tid = threadIdx.x;
    size_t i = (size_t)blockIdx.x * blockDim.x + tid;
    size_t stride = (size_t)gridDim.x * blockDim.x;
    const float4* X4 = (const float4*)X;
    float m = 0.0f;
    for (; i < n4; i += stride) {
        float4 v = X4[i];
        m = fmaxf(m, fmaxf(fmaxf(fabsf(v.x), fabsf(v.y)),
                           fmaxf(fabsf(v.z), fabsf(v.w))));
    }
#pragma unroll
    for (int o = 16; o; o >>= 1) m = fmaxf(m, __shfl_xor_sync(0xffffffffu, m, o));
    if ((tid & 31) == 0) red[tid >> 5] = m;
    __syncthreads();
    if (tid == 0) {
        float mm = red[0];
#pragma unroll
        for (int w = 1; w < 8; w++) mm = fmaxf(mm, red[w]);
        // abs values are >= 0, so float bit pattern order == uint order
        atomicMax(out, __float_as_uint(mm));
    }
}

__global__ void __launch_bounds__(256)
qdq_x_kernel(const float* __restrict__ X, float* __restrict__ Xq,
             const unsigned int* __restrict__ amax, size_t n4) {
    float s = __fdiv_rn(__uint_as_float(*amax), 127.0f) + 1e-12f;
    int tid = threadIdx.x;
    size_t i = (size_t)blockIdx.x * blockDim.x + tid;
    size_t stride = (size_t)gridDim.x * blockDim.x;
    const float4* X4 = (const float4*)X;
    float4* O4 = (float4*)Xq;
    for (; i < n4; i += stride) {
        float4 v = X4[i];
        v.x = qdqf(v.x, s); v.y = qdqf(v.y, s);
        v.z = qdqf(v.z, s); v.w = qdqf(v.w, s);
        O4[i] = v;
    }
}

// ---------------------------------------------------------------------------
// TN SGEMM: C[m,n] = sum_k A[m,k]*B[n,k]  (+bias, optional relu, optional qdq)
// Optional qdq of A elements on load (scale from abs-max buffer), for the
// attention-context requantization fused into the O projection.
// Tiles: 128x128x16, 256 threads, 8x8 per thread with 64-split fragments.
__global__ void __launch_bounds__(256, 2)
gemm_tn(const float* __restrict__ A, const float* __restrict__ Bw,
        float* __restrict__ C, int lda, int ldb, int ldc, int K,
        const float* __restrict__ bias,
        const float* __restrict__ opsc, int sidx, int relu,
        const unsigned int* __restrict__ amax) {
    __shared__ float As[16][128];
    __shared__ float Bs[16][128];
    const int tid = threadIdx.x;
    const int tx = tid & 15, ty = tid >> 4;
    const size_t bm = (size_t)blockIdx.y * 128;
    const size_t bn = (size_t)blockIdx.x * 128;

    const bool do_qa = (amax != nullptr);
    float a_scale = 1.0f;
    if (do_qa) a_scale = __fdiv_rn(__uint_as_float(*amax), 127.0f) + 1e-12f;

    float acc[8][8];
#pragma unroll
    for (int i = 0; i < 8; i++)
#pragma unroll
        for (int j = 0; j < 8; j++) acc[i][j] = 0.0f;

    for (int k0 = 0; k0 < K; k0 += 16) {
#pragma unroll
        for (int i = 0; i < 2; i++) {
            int idx = tid + i * 256;          // 0..511 over 512 float4s
            int row = idx >> 2;
            int kq  = (idx & 3) << 2;
            float4 va = *(const float4*)(A + (bm + row) * (size_t)lda + (k0 + kq));
            if (do_qa) {
                va.x = qdqf(va.x, a_scale); va.y = qdqf(va.y, a_scale);
                va.z = qdqf(va.z, a_scale); va.w = qdqf(va.w, a_scale);
            }
            As[kq + 0][row] = va.x; As[kq + 1][row] = va.y;
            As[kq + 2][row] = va.z; As[kq + 3][row] = va.w;
            float4 vb = *(const float4*)(Bw + (bn + row) * (size_t)ldb + (k0 + kq));
            Bs[kq + 0][row] = vb.x; Bs[kq + 1][row] = vb.y;
            Bs[kq + 2][row] = vb.z; Bs[kq + 3][row] = vb.w;
        }
        __syncthreads();
#pragma unroll
        for (int kk = 0; kk < 16; kk++) {
            float a0[4], a1[4], b0[4], b1[4];
            *(float4*)a0 = *(const float4*)&As[kk][ty * 4];
            *(float4*)a1 = *(const float4*)&As[kk][64 + ty * 4];
            *(float4*)b0 = *(const float4*)&Bs[kk][tx * 4];
            *(float4*)b1 = *(const float4*)&Bs[kk][64 + tx * 4];
#pragma unroll
            for (int i = 0; i < 4; i++)
#pragma unroll
                for (int j = 0; j < 4; j++) {
                    acc[i][j]         += a0[i] * b0[j];
                    acc[i][j + 4]     += a0[i] * b1[j];
                    acc[i + 4][j]     += a1[i] * b0[j];
                    acc[i + 4][j + 4] += a1[i] * b1[j];
                }
        }
        __syncthreads();
    }

    float s = (sidx >= 0) ? opsc[sidx] * 0.05f : 0.0f;
#pragma unroll
    for (int i = 0; i < 8; i++) {
        int r = (i < 4) ? (ty * 4 + i) : (64 + ty * 4 + i - 4);
#pragma unroll
        for (int half = 0; half < 2; half++) {
            int c0 = half * 64 + tx * 4;
            float4 v;
            v.x = acc[i][half * 4 + 0]; v.y = acc[i][half * 4 + 1];
            v.z = acc[i][half * 4 + 2]; v.w = acc[i][half * 4 + 3];
            if (bias) {
                float4 b4 = *(const float4*)(bias + bn + c0);
                v.x += b4.x; v.y += b4.y; v.z += b4.z; v.w += b4.w;
            }
            if (relu) {
                v.x = fmaxf(v.x, 0.0f); v.y = fmaxf(v.y, 0.0f);
                v.z = fmaxf(v.z, 0.0f); v.w = fmaxf(v.w, 0.0f);
            }
            if (sidx >= 0) {
                v.x = qdqf(v.x, s); v.y = qdqf(v.y, s);
                v.z = qdqf(v.z, s); v.w = qdqf(v.w, s);
            }
            *(float4*)(C + (bm + r) * (size_t)ldc + bn + c0) = v;
        }
    }
}

// ---------------------------------------------------------------------------
// Fused flash-style attention (fp32, exact expf, online softmax).
// Block: 128 q-rows x one (b,h); streams K/V in 64-key tiles.
// ctx[b,q,h,:] = softmax(Q.K^T/8) @ V
#define AT_TQ 128
#define AT_TK 64
#define QS_LD 132   // (AT_TQ + 4)
#define KS_LD 68    // (AT_TK + 4)
#define PS_LD 68

__global__ void __launch_bounds__(256, 2)
attn_fused(const float* __restrict__ Q, const float* __restrict__ K,
           const float* __restrict__ V, float* __restrict__ Ctx) {
    extern __shared__ float sm[];
    float* Qs = sm;                        // [64][QS_LD]  k-major: Qs[kk][r]
    float* Ks = Qs + 64 * QS_LD;           // [64][KS_LD]  k-major: Ks[kk][c]
    float* Vs = Ks + 64 * KS_LD;           // [64][KS_LD]  Vs[kt][d]
    float* Ps = Vs + 64 * KS_LD;           // [128][PS_LD] Ps[r][kt]

    const int tid = threadIdx.x;
    const int tx = tid & 15, ty = tid >> 4;
    const int z = blockIdx.y, b = z >> 4, h = z & 15;
    const size_t bm = (size_t)blockIdx.x * AT_TQ;
    const float* Qg = Q + ((size_t)b * SS) * DD + h * HD;
    const float* Kg = K + ((size_t)b * SS) * DD + h * HD;
    const float* Vg = V + ((size_t)b * SS) * DD + h * HD;

    // Load Q tile (transposed to k-major)
#pragma unroll
    for (int i = 0; i < 8; i++) {
        int idx = tid + i * 256;           // 0..2047
        int r = idx >> 4;                  // 0..127
        int q = (idx & 15) << 2;           // 0..60
        float4 v = *(const float4*)(Qg + (bm + r) * (size_t)DD + q);
        Qs[(q + 0) * QS_LD + r] = v.x; Qs[(q + 1) * QS_LD + r] = v.y;
        Qs[(q + 2) * QS_LD + r] = v.z; Qs[(q + 3) * QS_LD + r] = v.w;
    }

    float m_reg[8], l_reg[8], acc[8][4];
#pragma unroll
    for (int i = 0; i < 8; i++) {
        m_reg[i] = -1e30f; l_reg[i] = 0.0f;
#pragma unroll
        for (int j = 0; j < 4; j++) acc[i][j] = 0.0f;
    }

    for (int kt0 = 0; kt0 < SS; kt0 += AT_TK) {
        __syncthreads();   // prev iter done reading Ks/Vs/Ps
        // Load K tile (transposed) and V tile
#pragma unroll
        for (int i = 0; i < 4; i++) {
            int idx = tid + i * 256;       // 0..1023
            int c = idx >> 4;              // key 0..63
            int q = (idx & 15) << 2;
            float4 kv = *(const float4*)(Kg + (size_t)(kt0 + c) * DD + q);
            Ks[(q + 0) * KS_LD + c] = kv.x; Ks[(q + 1) * KS_LD + c] = kv.y;
            Ks[(q + 2) * KS_LD + c] = kv.z; Ks[(q + 3) * KS_LD + c] = kv.w;
            float4 vv = *(const float4*)(Vg + (size_t)(kt0 + c) * DD + q);
            *(float4*)&Vs[c * KS_LD + q] = vv;
        }
        __syncthreads();

        // S = Q.K^T / 8 for this tile (8 rows x 4 cols per thread)
        float s[8][4];
#pragma unroll
        for (int i = 0; i < 8; i++)
#pragma unroll
            for (int j = 0; j < 4; j++) s[i][j] = 0.0f;
#pragma unroll 4
        for (int kk = 0; kk < 64; kk++) {
            float a[8], bb[4];
            *(float4*)&a[0] = *(const float4*)&Qs[kk * QS_LD + ty * 8];
            *(float4*)&a[4] = *(const float4*)&Qs[kk * QS_LD + ty * 8 + 4];
            *(float4*)&bb[0] = *(const float4*)&Ks[kk * KS_LD + tx * 4];
#pragma unroll
            for (int i = 0; i < 8; i++)
#pragma unroll
                for (int j = 0; j < 4; j++) s[i][j] += a[i] * bb[j];
        }

        // Online softmax update; write P tile
#pragma unroll
        for (int i = 0; i < 8; i++) {
            float mx = fmaxf(fmaxf(s[i][0], s[i][1]), fmaxf(s[i][2], s[i][3]));
            mx *= 0.125f;
#pragma unroll
            for (int o = 8; o; o >>= 1)
                mx = fmaxf(mx, __shfl_xor_sync(0xffffffffu, mx, o));
            float mn = fmaxf(m_reg[i], mx);
            float alpha = expf(m_reg[i] - mn);
            float ps = 0.0f;
            float4 p4;
            p4.x = expf(s[i][0] * 0.125f - mn);
            p4.y = expf(s[i][1] * 0.125f - mn);
            p4.z = expf(s[i][2] * 0.125f - mn);
            p4.w = expf(s[i][3] * 0.125f - mn);
            *(float4*)&Ps[(ty * 8 + i) * PS_LD + tx * 4] = p4;
            ps = (p4.x + p4.y) + (p4.z + p4.w);
#pragma unroll
            for (int o = 8; o; o >>= 1)
                ps += __shfl_xor_sync(0xffffffffu, ps, o);
            l_reg[i] = l_reg[i] * alpha + ps;
            m_reg[i] = mn;
#pragma unroll
            for (int j = 0; j < 4; j++) acc[i][j] *= alpha;
        }
        __syncthreads();

        // acc += P @ V
#pragma unroll 4
        for (int kt = 0; kt < 64; kt++) {
            float a[8], bb[4];
#pragma unroll
            for (int i = 0; i < 8; i++) a[i] = Ps[(ty * 8 + i) * PS_LD + kt];
            *(float4*)&bb[0] = *(const float4*)&Vs[kt * KS_LD + tx * 4];
#pragma unroll
            for (int i = 0; i < 8; i++)
#pragma unroll
                for (int j = 0; j < 4; j++) acc[i][j] += a[i] * bb[j];
        }
    }

    // Finalize: divide by row sums, write ctx (layout [b, q, h, d])
    float* Cg = Ctx + ((size_t)b * SS) * DD + h * HD;
#pragma unroll
    for (int i = 0; i < 8; i++) {
        float inv = __fdiv_rn(1.0f, l_reg[i]);
        float4 v;
        v.x = acc[i][0] * inv; v.y = acc[i][1] * inv;
        v.z = acc[i][2] * inv; v.w = acc[i][3] * inv;
        *(float4*)(Cg + (bm + ty * 8 + i) * (size_t)DD + tx * 4) = v;
    }
}

// ---------------------------------------------------------------------------
// t = qdq(X+Y, s[sa]); Out = qdq(layernorm(t)*w+b, s[sl]). One block per row.
__global__ void __launch_bounds__(256)
add_ln(const float* __restrict__ X, const float* __restrict__ Y,
       const float* __restrict__ w, const float* __restrict__ bvec,
       const float* __restrict__ opsc, int sa, int sl,
       float* __restrict__ Out) {
    __shared__ float red[8];
    const int tid = threadIdx.x;
    const size_t base = (size_t)blockIdx.x * 1024;
    const float s_add = opsc[sa] * 0.05f;
    const float s_ln  = opsc[sl] * 0.05f;
    const int c = tid * 4;
    float4 xv = *(const float4*)(X + base + c);
    float4 yv = *(const float4*)(Y + base + c);
    float v0 = qdqf(xv.x + yv.x, s_add);
    float v1 = qdqf(xv.y + yv.y, s_add);
    float v2 = qdqf(xv.z + yv.z, s_add);
    float v3 = qdqf(xv.w + yv.w, s_add);

    float lsum = (v0 + v1) + (v2 + v3);
#pragma unroll
    for (int o = 16; o; o >>= 1) lsum += __shfl_xor_sync(0xffffffffu, lsum, o);
    if ((tid & 31) == 0) red[tid >> 5] = lsum;
    __syncthreads();
    float tot = 0.0f;
#pragma unroll
    for (int ww = 0; ww < 8; ww++) tot += red[ww];
    float mu = tot * (1.0f / 1024.0f);

    float d0 = v0 - mu, d1 = v1 - mu, d2 = v2 - mu, d3 = v3 - mu;
    float lv = d0 * d0 + d1 * d1 + d2 * d2 + d3 * d3;
#pragma unroll
    for (int o = 16; o; o >>= 1) lv += __shfl_xor_sync(0xffffffffu, lv, o);
    __syncthreads();
    if ((tid & 31) == 0) red[tid >> 5] = lv;
    __syncthreads();
    float vtot = 0.0f;
#pragma unroll
    for (int ww = 0; ww < 8; ww++) vtot += red[ww];
    float var = vtot * (1.0f / 1024.0f);
    float rstd = __fdiv_rn(1.0f, __fsqrt_rn(var + 1e-5f));

    float4 w4 = *(const float4*)(w + c);
    float4 b4 = *(const float4*)(bvec + c);
    float4 o4;
    o4.x = qdqf(d0 * rstd * w4.x + b4.x, s_ln);
    o4.y = qdqf(d1 * rstd * w4.y + b4.y, s_ln);
    o4.z = qdqf(d2 * rstd * w4.z + b4.z, s_ln);
    o4.w = qdqf(d3 * rstd * w4.w + b4.w, s_ln);
    *(float4*)(Out + base + c) = o4;
}

// ---------------------------------------------------------------------------
extern "C" void kernel_launch(void* const* d_in, const int* in_sizes, int n_in,
                              void* d_out, int out_size) {
    const float* x    = (const float*)d_in[0];
    // d_in[1] = attn_mask (all-true for this problem; masking is a no-op)
    const float* wq   = (const float*)d_in[2];
    const float* bq   = (const float*)d_in[3];
    const float* wk   = (const float*)d_in[4];
    const float* bk   = (const float*)d_in[5];
    const float* wv   = (const float*)d_in[6];
    const float* bv   = (const float*)d_in[7];
    const float* wo   = (const float*)d_in[8];
    const float* bo   = (const float*)d_in[9];
    const float* w1   = (const float*)d_in[10];
    const float* b1   = (const float*)d_in[11];
    const float* w2   = (const float*)d_in[12];
    const float* b2   = (const float*)d_in[13];
    const float* ln1w = (const float*)d_in[14];
    const float* ln1b = (const float*)d_in[15];
    const float* ln2w = (const float*)d_in[16];
    const float* ln2b = (const float*)d_in[17];
    const float* opsc = (const float*)d_in[18];
    float* out = (float*)d_out;

    float *xq, *q, *k, *v, *ctx, *o, *h, *f, *f2;
    unsigned int* amax;
    cudaGetSymbolAddress((void**)&xq,  g_xq);
    cudaGetSymbolAddress((void**)&q,   g_q);
    cudaGetSymbolAddress((void**)&k,   g_k);
    cudaGetSymbolAddress((void**)&v,   g_v);
    cudaGetSymbolAddress((void**)&ctx, g_ctx);
    cudaGetSymbolAddress((void**)&o,   g_o);
    cudaGetSymbolAddress((void**)&h,   g_h);
    cudaGetSymbolAddress((void**)&f,   g_f);
    cudaGetSymbolAddress((void**)&f2,  g_f2);
    cudaGetSymbolAddress((void**)&amax, g_amax);

    // fused attention needs > 48 KB dynamic smem
    static const int ATT_SMEM = (64 * QS_LD + 64 * KS_LD + 64 * KS_LD + 128 * PS_LD) * 4;
    cudaFuncSetAttribute(attn_fused, cudaFuncAttributeMaxDynamicSharedMemorySize, ATT_SMEM);

    init_amax_kernel<<<1, 32>>>();

    // input quantization (dynamic per-tensor scale)
    absmax_kernel<<<1024, 256>>>(x, NX / 4, amax + 0);
    qdq_x_kernel<<<2048, 256>>>(x, xq, amax + 0, NX / 4);

    // QKV projections (note reference wiring: k <- (wv,bv), v <- (wk,bk))
    dim3 g64(8, 64);
    gemm_tn<<<g64, 256>>>(xq, wq, q, DD, DD, DD, DD, bq, opsc, 0, 0, nullptr);
    gemm_tn<<<g64, 256>>>(xq, wv, k, DD, DD, DD, DD, bv, opsc, 1, 0, nullptr);
    gemm_tn<<<g64, 256>>>(xq, wk, v, DD, DD, DD, DD, bk, opsc, 2, 0, nullptr);

    // fused attention (scores + softmax + ctx), no materialized score tensor
    attn_fused<<<dim3(SS / AT_TQ, BB * HH), 256, ATT_SMEM>>>(q, k, v, ctx);

    // requantize ctx (dynamic scale) fused into the O projection's A-load
    absmax_kernel<<<1024, 256>>>(ctx, NX / 4, amax + 1);
    gemm_tn<<<g64, 256>>>(ctx, wo, o, DD, DD, DD, DD, bo, opsc, 3, 0, amax + 1);

    // residual + LN1
    add_ln<<<BB * SS, 256>>>(xq, o, ln1w, ln1b, opsc, 8, 6, h);

    // FFN
    gemm_tn<<<dim3(32, 64), 256>>>(h, w1, f,  DD, DD, FF, DD, b1, opsc, 4, 1, nullptr);
    gemm_tn<<<dim3(8, 64), 256>>>(f, w2, f2, FF, FF, DD, FF, b2, opsc, 5, 0, nullptr);

    // residual + LN2 -> output
    add_ln<<<BB * SS, 256>>>(h, f2, ln2w, ln2b, opsc, 9, 7, out);
}

// round 4
// speedup vs baseline: 1.0114x; 1.0114x over previous
#include <cuda_runtime.h>
#include <math.h>
#include <stdint.h>
#include <stddef.h>

// Problem dims (fixed)
#define BB 4
#define SS 2048
#define DD 1024
#define HH 16
#define HD 64
#define FF 4096

static const size_t NX = (size_t)BB * SS * DD;        // 8388608

// Scratch (device globals; allocation APIs are forbidden)
__device__ float g_xq [8388608];
__device__ float g_q  [8388608];
__device__ float g_k  [8388608];
__device__ float g_v  [8388608];
__device__ float g_ctx[8388608];
__device__ float g_o  [8388608];
__device__ float g_h  [8388608];
__device__ float g_f  [33554432];
__device__ float g_f2 [8388608];
__device__ unsigned int g_amax[2];

// ---------------------------------------------------------------------------
// qdq: quantize_per_tensor(zp=64, quint8) + dequantize, matching
//   q = clip(round(x/scale)+64, 0, 255); (q-64)*scale
// with IEEE division and round-half-to-even to match the JAX fp32 reference.
__device__ __forceinline__ float qdqf(float x, float s) {
    float r = rintf(__fdiv_rn(x, s));
    r = fminf(fmaxf(r + 64.0f, 0.0f), 255.0f);
    return (r - 64.0f) * s;
}

// ---------------------------------------------------------------------------
__global__ void __launch_bounds__(32)
init_amax_kernel() {
    if (threadIdx.x < 2) g_amax[threadIdx.x] = 0u;
}

__global__ void __launch_bounds__(256)
absmax_kernel(const float* __restrict__ X, size_t n4, unsigned int* __restrict__ out) {
    __shared__ float red[8];
    int tid = threadIdx.x;
    size_t i = (size_t)blockIdx.x * blockDim.x + tid;
    size_t stride = (size_t)gridDim.x * blockDim.x;
    const float4* X4 = (const float4*)X;
    float m = 0.0f;
    for (; i < n4; i += stride) {
        float4 v = X4[i];
        m = fmaxf(m, fmaxf(fmaxf(fabsf(v.x), fabsf(v.y)),
                           fmaxf(fabsf(v.z), fabsf(v.w))));
    }
#pragma unroll
    for (int o = 16; o; o >>= 1) m = fmaxf(m, __shfl_xor_sync(0xffffffffu, m, o));
    if ((tid & 31) == 0) red[tid >> 5] = m;
    __syncthreads();
    if (tid == 0) {
        float mm = red[0];
#pragma unroll
        for (int w = 1; w < 8; w++) mm = fmaxf(mm, red[w]);
        // abs values are >= 0, so float bit pattern order == uint order
        atomicMax(out, __float_as_uint(mm));
    }
}

__global__ void __launch_bounds__(256)
qdq_x_kernel(const float* __restrict__ X, float* __restrict__ Xq,
             const unsigned int* __restrict__ amax, size_t n4) {
    float s = __fdiv_rn(__uint_as_float(*amax), 127.0f) + 1e-12f;
    int tid = threadIdx.x;
    size_t i = (size_t)blockIdx.x * blockDim.x + tid;
    size_t stride = (size_t)gridDim.x * blockDim.x;
    const float4* X4 = (const float4*)X;
    float4* O4 = (float4*)Xq;
    for (; i < n4; i += stride) {
        float4 v = X4[i];
        v.x = qdqf(v.x, s); v.y = qdqf(v.y, s);
        v.z = qdqf(v.z, s); v.w = qdqf(v.w, s);
        O4[i] = v;
    }
}

// ---------------------------------------------------------------------------
// TN SGEMM: C[m,n] = sum_k A[m,k]*B[n,k]  (+bias, optional relu, optional qdq)
// Tiles: 128x128x16, 256 threads, 8x8/thread with 64-split fragments.
// Register-staged double-buffered smem pipeline, ONE syncthreads per K-chunk:
//   store staged(chunk c) -> buf[c&1]; sync; LDG chunk c+1 -> staged; compute.
// The FFMA inner loop body is identical to the R2 kernel => bitwise-identical C.
__global__ void __launch_bounds__(256, 2)
gemm_tn(const float* __restrict__ A, const float* __restrict__ Bw,
        float* __restrict__ C, int lda, int ldb, int ldc, int K,
        const float* __restrict__ bias,
        const float* __restrict__ opsc, int sidx, int relu) {
    __shared__ float As[2][16][128];
    __shared__ float Bs[2][16][128];
    const int tid = threadIdx.x;
    const int tx = tid & 15, ty = tid >> 4;
    const size_t bm = (size_t)blockIdx.y * 128;
    const size_t bn = (size_t)blockIdx.x * 128;

    // per-thread load coords (2 float4 for A, 2 for B per chunk)
    const int r0 = tid >> 2;                 // 0..63
    const int r1 = (tid + 256) >> 2;         // 64..127
    const int kq = (tid & 3) << 2;           // 0,4,8,12

    const float* Ap0 = A + (bm + r0) * (size_t)lda + kq;
    const float* Ap1 = A + (bm + r1) * (size_t)lda + kq;
    const float* Bp0 = Bw + (bn + r0) * (size_t)ldb + kq;
    const float* Bp1 = Bw + (bn + r1) * (size_t)ldb + kq;

    float acc[8][8];
#pragma unroll
    for (int i = 0; i < 8; i++)
#pragma unroll
        for (int j = 0; j < 8; j++) acc[i][j] = 0.0f;

    // prologue: stage chunk 0
    float4 ra0 = *(const float4*)(Ap0);
    float4 ra1 = *(const float4*)(Ap1);
    float4 rb0 = *(const float4*)(Bp0);
    float4 rb1 = *(const float4*)(Bp1);

    const int NC = K >> 4;
    for (int c = 0; c < NC; c++) {
        const int buf = c & 1;
        // store staged chunk into smem (transposed to k-major)
        As[buf][kq + 0][r0] = ra0.x; As[buf][kq + 1][r0] = ra0.y;
        As[buf][kq + 2][r0] = ra0.z; As[buf][kq + 3][r0] = ra0.w;
        As[buf][kq + 0][r1] = ra1.x; As[buf][kq + 1][r1] = ra1.y;
        As[buf][kq + 2][r1] = ra1.z; As[buf][kq + 3][r1] = ra1.w;
        Bs[buf][kq + 0][r0] = rb0.x; Bs[buf][kq + 1][r0] = rb0.y;
        Bs[buf][kq + 2][r0] = rb0.z; Bs[buf][kq + 3][r0] = rb0.w;
        Bs[buf][kq + 0][r1] = rb1.x; Bs[buf][kq + 1][r1] = rb1.y;
        Bs[buf][kq + 2][r1] = rb1.z; Bs[buf][kq + 3][r1] = rb1.w;
        __syncthreads();

        // issue global loads for next chunk (latency hidden by compute below)
        if (c + 1 < NC) {
            const int ko = (c + 1) << 4;
            ra0 = *(const float4*)(Ap0 + ko);
            ra1 = *(const float4*)(Ap1 + ko);
            rb0 = *(const float4*)(Bp0 + ko);
            rb1 = *(const float4*)(Bp1 + ko);
        }

#pragma unroll
        for (int kk = 0; kk < 16; kk++) {
            float a0[4], a1[4], b0[4], b1[4];
            *(float4*)a0 = *(const float4*)&As[buf][kk][ty * 4];
            *(float4*)a1 = *(const float4*)&As[buf][kk][64 + ty * 4];
            *(float4*)b0 = *(const float4*)&Bs[buf][kk][tx * 4];
            *(float4*)b1 = *(const float4*)&Bs[buf][kk][64 + tx * 4];
#pragma unroll
            for (int i = 0; i < 4; i++)
#pragma unroll
                for (int j = 0; j < 4; j++) {
                    acc[i][j]         += a0[i] * b0[j];
                    acc[i][j + 4]     += a0[i] * b1[j];
                    acc[i + 4][j]     += a1[i] * b0[j];
                    acc[i + 4][j + 4] += a1[i] * b1[j];
                }
        }
    }

    float s = (sidx >= 0) ? opsc[sidx] * 0.05f : 0.0f;
#pragma unroll
    for (int i = 0; i < 8; i++) {
        int r = (i < 4) ? (ty * 4 + i) : (64 + ty * 4 + i - 4);
#pragma unroll
        for (int half = 0; half < 2; half++) {
            int c0 = half * 64 + tx * 4;
            float4 v;
            v.x = acc[i][half * 4 + 0]; v.y = acc[i][half * 4 + 1];
            v.z = acc[i][half * 4 + 2]; v.w = acc[i][half * 4 + 3];
            if (bias) {
                float4 b4 = *(const float4*)(bias + bn + c0);
                v.x += b4.x; v.y += b4.y; v.z += b4.z; v.w += b4.w;
            }
            if (relu) {
                v.x = fmaxf(v.x, 0.0f); v.y = fmaxf(v.y, 0.0f);
                v.z = fmaxf(v.z, 0.0f); v.w = fmaxf(v.w, 0.0f);
            }
            if (sidx >= 0) {
                v.x = qdqf(v.x, s); v.y = qdqf(v.y, s);
                v.z = qdqf(v.z, s); v.w = qdqf(v.w, s);
            }
            *(float4*)(C + (bm + r) * (size_t)ldc + bn + c0) = v;
        }
    }
}

// ---------------------------------------------------------------------------
// Fused flash-style attention (fp32, exact expf, online softmax).
// Block: 128 q-rows x one (b,h); streams K/V in 64-key tiles.
// ctx[b,q,h,:] = softmax(Q.K^T/8) @ V
#define AT_TQ 128
#define AT_TK 64
#define QS_LD 132   // (AT_TQ + 4)
#define KS_LD 68    // (AT_TK + 4)
#define PS_LD 68

__global__ void __launch_bounds__(256, 2)
attn_fused(const float* __restrict__ Q, const float* __restrict__ K,
           const float* __restrict__ V, float* __restrict__ Ctx) {
    extern __shared__ float sm[];
    float* Qs = sm;                        // [64][QS_LD]  k-major: Qs[kk][r]
    float* Ks = Qs + 64 * QS_LD;           // [64][KS_LD]  k-major: Ks[kk][c]
    float* Vs = Ks + 64 * KS_LD;           // [64][KS_LD]  Vs[kt][d]
    float* Ps = Vs + 64 * KS_LD;           // [128][PS_LD] Ps[r][kt]

    const int tid = threadIdx.x;
    const int tx = tid & 15, ty = tid >> 4;
    const int z = blockIdx.y, b = z >> 4, h = z & 15;
    const size_t bm = (size_t)blockIdx.x * AT_TQ;
    const float* Qg = Q + ((size_t)b * SS) * DD + h * HD;
    const float* Kg = K + ((size_t)b * SS) * DD + h * HD;
    const float* Vg = V + ((size_t)b * SS) * DD + h * HD;

    // Load Q tile (transposed to k-major)
#pragma unroll
    for (int i = 0; i < 8; i++) {
        int idx = tid + i * 256;           // 0..2047
        int r = idx >> 4;                  // 0..127
        int q = (idx & 15) << 2;           // 0..60
        float4 v = *(const float4*)(Qg + (bm + r) * (size_t)DD + q);
        Qs[(q + 0) * QS_LD + r] = v.x; Qs[(q + 1) * QS_LD + r] = v.y;
        Qs[(q + 2) * QS_LD + r] = v.z; Qs[(q + 3) * QS_LD + r] = v.w;
    }

    float m_reg[8], l_reg[8], acc[8][4];
#pragma unroll
    for (int i = 0; i < 8; i++) {
        m_reg[i] = -1e30f; l_reg[i] = 0.0f;
#pragma unroll
        for (int j = 0; j < 4; j++) acc[i][j] = 0.0f;
    }

    for (int kt0 = 0; kt0 < SS; kt0 += AT_TK) {
        __syncthreads();   // prev iter done reading Ks/Vs/Ps
        // Load K tile (transposed) and V tile
#pragma unroll
        for (int i = 0; i < 4; i++) {
            int idx = tid + i * 256;       // 0..1023
            int c = idx >> 4;              // key 0..63
            int q = (idx & 15) << 2;
            float4 kv = *(const float4*)(Kg + (size_t)(kt0 + c) * DD + q);
            Ks[(q + 0) * KS_LD + c] = kv.x; Ks[(q + 1) * KS_LD + c] = kv.y;
            Ks[(q + 2) * KS_LD + c] = kv.z; Ks[(q + 3) * KS_LD + c] = kv.w;
            float4 vv = *(const float4*)(Vg + (size_t)(kt0 + c) * DD + q);
            *(float4*)&Vs[c * KS_LD + q] = vv;
        }
        __syncthreads();

        // S = Q.K^T / 8 for this tile (8 rows x 4 cols per thread)
        float s[8][4];
#pragma unroll
        for (int i = 0; i < 8; i++)
#pragma unroll
            for (int j = 0; j < 4; j++) s[i][j] = 0.0f;
#pragma unroll 4
        for (int kk = 0; kk < 64; kk++) {
            float a[8], bb[4];
            *(float4*)&a[0] = *(const float4*)&Qs[kk * QS_LD + ty * 8];
            *(float4*)&a[4] = *(const float4*)&Qs[kk * QS_LD + ty * 8 + 4];
            *(float4*)&bb[0] = *(const float4*)&Ks[kk * KS_LD + tx * 4];
#pragma unroll
            for (int i = 0; i < 8; i++)
#pragma unroll
                for (int j = 0; j < 4; j++) s[i][j] += a[i] * bb[j];
        }

        // Online softmax update; write P tile
#pragma unroll
        for (int i = 0; i < 8; i++) {
            float mx = fmaxf(fmaxf(s[i][0], s[i][1]), fmaxf(s[i][2], s[i][3]));
            mx *= 0.125f;
#pragma unroll
            for (int o = 8; o; o >>= 1)
                mx = fmaxf(mx, __shfl_xor_sync(0xffffffffu, mx, o));
            float mn = fmaxf(m_reg[i], mx);
            float alpha = expf(m_reg[i] - mn);
            float ps = 0.0f;
            float4 p4;
            p4.x = expf(s[i][0] * 0.125f - mn);
            p4.y = expf(s[i][1] * 0.125f - mn);
            p4.z = expf(s[i][2] * 0.125f - mn);
            p4.w = expf(s[i][3] * 0.125f - mn);
            *(float4*)&Ps[(ty * 8 + i) * PS_LD + tx * 4] = p4;
            ps = (p4.x + p4.y) + (p4.z + p4.w);
#pragma unroll
            for (int o = 8; o; o >>= 1)
                ps += __shfl_xor_sync(0xffffffffu, ps, o);
            l_reg[i] = l_reg[i] * alpha + ps;
            m_reg[i] = mn;
#pragma unroll
            for (int j = 0; j < 4; j++) acc[i][j] *= alpha;
        }
        __syncthreads();

        // acc += P @ V
#pragma unroll 4
        for (int kt = 0; kt < 64; kt++) {
            float a[8], bb[4];
#pragma unroll
            for (int i = 0; i < 8; i++) a[i] = Ps[(ty * 8 + i) * PS_LD + kt];
            *(float4*)&bb[0] = *(const float4*)&Vs[kt * KS_LD + tx * 4];
#pragma unroll
            for (int i = 0; i < 8; i++)
#pragma unroll
                for (int j = 0; j < 4; j++) acc[i][j] += a[i] * bb[j];
        }
    }

    // Finalize: divide by row sums, write ctx (layout [b, q, h, d])
    float* Cg = Ctx + ((size_t)b * SS) * DD + h * HD;
#pragma unroll
    for (int i = 0; i < 8; i++) {
        float inv = __fdiv_rn(1.0f, l_reg[i]);
        float4 v;
        v.x = acc[i][0] * inv; v.y = acc[i][1] * inv;
        v.z = acc[i][2] * inv; v.w = acc[i][3] * inv;
        *(float4*)(Cg + (bm + ty * 8 + i) * (size_t)DD + tx * 4) = v;
    }
}

// ---------------------------------------------------------------------------
// t = qdq(X+Y, s[sa]); Out = qdq(layernorm(t)*w+b, s[sl]). One block per row.
__global__ void __launch_bounds__(256)
add_ln(const float* __restrict__ X, const float* __restrict__ Y,
       const float* __restrict__ w, const float* __restrict__ bvec,
       const float* __restrict__ opsc, int sa, int sl,
       float* __restrict__ Out) {
    __shared__ float red[8];
    const int tid = threadIdx.x;
    const size_t base = (size_t)blockIdx.x * 1024;
    const float s_add = opsc[sa] * 0.05f;
    const float s_ln  = opsc[sl] * 0.05f;
    const int c = tid * 4;
    float4 xv = *(const float4*)(X + base + c);
    float4 yv = *(const float4*)(Y + base + c);
    float v0 = qdqf(xv.x + yv.x, s_add);
    float v1 = qdqf(xv.y + yv.y, s_add);
    float v2 = qdqf(xv.z + yv.z, s_add);
    float v3 = qdqf(xv.w + yv.w, s_add);

    float lsum = (v0 + v1) + (v2 + v3);
#pragma unroll
    for (int o = 16; o; o >>= 1) lsum += __shfl_xor_sync(0xffffffffu, lsum, o);
    if ((tid & 31) == 0) red[tid >> 5] = lsum;
    __syncthreads();
    float tot = 0.0f;
#pragma unroll
    for (int ww = 0; ww < 8; ww++) tot += red[ww];
    float mu = tot * (1.0f / 1024.0f);

    float d0 = v0 - mu, d1 = v1 - mu, d2 = v2 - mu, d3 = v3 - mu;
    float lv = d0 * d0 + d1 * d1 + d2 * d2 + d3 * d3;
#pragma unroll
    for (int o = 16; o; o >>= 1) lv += __shfl_xor_sync(0xffffffffu, lv, o);
    __syncthreads();
    if ((tid & 31) == 0) red[tid >> 5] = lv;
    __syncthreads();
    float vtot = 0.0f;
#pragma unroll
    for (int ww = 0; ww < 8; ww++) vtot += red[ww];
    float var = vtot * (1.0f / 1024.0f);
    float rstd = __fdiv_rn(1.0f, __fsqrt_rn(var + 1e-5f));

    float4 w4 = *(const float4*)(w + c);
    float4 b4 = *(const float4*)(bvec + c);
    float4 o4;
    o4.x = qdqf(d0 * rstd * w4.x + b4.x, s_ln);
    o4.y = qdqf(d1 * rstd * w4.y + b4.y, s_ln);
    o4.z = qdqf(d2 * rstd * w4.z + b4.z, s_ln);
    o4.w = qdqf(d3 * rstd * w4.w + b4.w, s_ln);
    *(float4*)(Out + base + c) = o4;
}

// ---------------------------------------------------------------------------
extern "C" void kernel_launch(void* const* d_in, const int* in_sizes, int n_in,
                              void* d_out, int out_size) {
    const float* x    = (const float*)d_in[0];
    // d_in[1] = attn_mask (all-true for this problem; masking is a no-op)
    const float* wq   = (const float*)d_in[2];
    const float* bq   = (const float*)d_in[3];
    const float* wk   = (const float*)d_in[4];
    const float* bk   = (const float*)d_in[5];
    const float* wv   = (const float*)d_in[6];
    const float* bv   = (const float*)d_in[7];
    const float* wo   = (const float*)d_in[8];
    const float* bo   = (const float*)d_in[9];
    const float* w1   = (const float*)d_in[10];
    const float* b1   = (const float*)d_in[11];
    const float* w2   = (const float*)d_in[12];
    const float* b2   = (const float*)d_in[13];
    const float* ln1w = (const float*)d_in[14];
    const float* ln1b = (const float*)d_in[15];
    const float* ln2w = (const float*)d_in[16];
    const float* ln2b = (const float*)d_in[17];
    const float* opsc = (const float*)d_in[18];
    float* out = (float*)d_out;

    float *xq, *q, *k, *v, *ctx, *o, *h, *f, *f2;
    unsigned int* amax;
    cudaGetSymbolAddress((void**)&xq,  g_xq);
    cudaGetSymbolAddress((void**)&q,   g_q);
    cudaGetSymbolAddress((void**)&k,   g_k);
    cudaGetSymbolAddress((void**)&v,   g_v);
    cudaGetSymbolAddress((void**)&ctx, g_ctx);
    cudaGetSymbolAddress((void**)&o,   g_o);
    cudaGetSymbolAddress((void**)&h,   g_h);
    cudaGetSymbolAddress((void**)&f,   g_f);
    cudaGetSymbolAddress((void**)&f2,  g_f2);
    cudaGetSymbolAddress((void**)&amax, g_amax);

    // fused attention needs > 48 KB dynamic smem
    static const int ATT_SMEM = (64 * QS_LD + 64 * KS_LD + 64 * KS_LD + 128 * PS_LD) * 4;
    cudaFuncSetAttribute(attn_fused, cudaFuncAttributeMaxDynamicSharedMemorySize, ATT_SMEM);

    init_amax_kernel<<<1, 32>>>();

    // input quantization (dynamic per-tensor scale)
    absmax_kernel<<<1024, 256>>>(x, NX / 4, amax + 0);
    qdq_x_kernel<<<2048, 256>>>(x, xq, amax + 0, NX / 4);

    // QKV projections (note reference wiring: k <- (wv,bv), v <- (wk,bk))
    dim3 g64(8, 64);
    gemm_tn<<<g64, 256>>>(xq, wq, q, DD, DD, DD, DD, bq, opsc, 0, 0);
    gemm_tn<<<g64, 256>>>(xq, wv, k, DD, DD, DD, DD, bv, opsc, 1, 0);
    gemm_tn<<<g64, 256>>>(xq, wk, v, DD, DD, DD, DD, bk, opsc, 2, 0);

    // fused attention (scores + softmax + ctx), no materialized score tensor
    attn_fused<<<dim3(SS / AT_TQ, BB * HH), 256, ATT_SMEM>>>(q, k, v, ctx);

    // requantize ctx with dynamic scale (elementwise, into free q buffer),
    // then O projection
    absmax_kernel<<<1024, 256>>>(ctx, NX / 4, amax + 1);
    qdq_x_kernel<<<2048, 256>>>(ctx, q, amax + 1, NX / 4);
    gemm_tn<<<g64, 256>>>(q, wo, o, DD, DD, DD, DD, bo, opsc, 3, 0);

    // residual + LN1
    add_ln<<<BB * SS, 256>>>(xq, o, ln1w, ln1b, opsc, 8, 6, h);

    // FFN
    gemm_tn<<<dim3(32, 64), 256>>>(h, w1, f,  DD, DD, FF, DD, b1, opsc, 4, 1);
    gemm_tn<<<dim3(8, 64), 256>>>(f, w2, f2, FF, FF, DD, FF, b2, opsc, 5, 0);

    // residual + LN2 -> output
    add_ln<<<BB * SS, 256>>>(h, f2, ln2w, ln2b, opsc, 9, 7, out);
}

// round 5
// speedup vs baseline: 1.0578x; 1.0459x over previous
#include <cuda_runtime.h>
#include <math.h>
#include <stdint.h>
#include <stddef.h>

// Problem dims (fixed)
#define BB 4
#define SS 2048
#define DD 1024
#define HH 16
#define HD 64
#define FF 4096

static const size_t NX = (size_t)BB * SS * DD;        // 8388608

// Scratch (device globals; allocation APIs are forbidden)
__device__ float g_xq [8388608];
__device__ float g_q  [8388608];
__device__ float g_k  [8388608];
__device__ float g_v  [8388608];
__device__ float g_ctx[8388608];
__device__ float g_o  [8388608];
__device__ float g_h  [8388608];
__device__ float g_f  [33554432];
__device__ float g_f2 [8388608];
__device__ unsigned int g_amax[2];

// ---------------------------------------------------------------------------
// Packed f32x2 helpers (Blackwell sm_100+: one instr = two independent IEEE
// fp32 ops => bitwise-identical to the scalar FFMA chain per element).
typedef unsigned long long u64t;

__device__ __forceinline__ u64t pack2(float x, float y) {
    u64t r;
    asm("mov.b64 %0, {%1, %2};" : "=l"(r) : "f"(x), "f"(y));
    return r;
}
__device__ __forceinline__ u64t bcast2(float x) {
    u64t r;
    asm("mov.b64 %0, {%1, %1};" : "=l"(r) : "f"(x));
    return r;
}
__device__ __forceinline__ void fma2(u64t& acc, u64t a, u64t b) {
    asm("fma.rn.f32x2 %0, %1, %2, %0;" : "+l"(acc) : "l"(a), "l"(b));
}
__device__ __forceinline__ void mul2(u64t& acc, u64t s) {
    asm("mul.rn.f32x2 %0, %0, %1;" : "+l"(acc) : "l"(s));
}
__device__ __forceinline__ void unpack2(u64t v, float& x, float& y) {
    asm("mov.b64 {%0, %1}, %2;" : "=f"(x), "=f"(y) : "l"(v));
}

// ---------------------------------------------------------------------------
// qdq: quantize_per_tensor(zp=64, quint8) + dequantize, matching
//   q = clip(round(x/scale)+64, 0, 255); (q-64)*scale
// with IEEE division and round-half-to-even to match the JAX fp32 reference.
__device__ __forceinline__ float qdqf(float x, float s) {
    float r = rintf(__fdiv_rn(x, s));
    r = fminf(fmaxf(r + 64.0f, 0.0f), 255.0f);
    return (r - 64.0f) * s;
}

// ---------------------------------------------------------------------------
__global__ void __launch_bounds__(32)
init_amax_kernel() {
    if (threadIdx.x < 2) g_amax[threadIdx.x] = 0u;
}

__global__ void __launch_bounds__(256)
absmax_kernel(const float* __restrict__ X, size_t n4, unsigned int* __restrict__ out) {
    __shared__ float red[8];
    int tid = threadIdx.x;
    size_t i = (size_t)blockIdx.x * blockDim.x + tid;
    size_t stride = (size_t)gridDim.x * blockDim.x;
    const float4* X4 = (const float4*)X;
    float m = 0.0f;
    for (; i < n4; i += stride) {
        float4 v = X4[i];
        m = fmaxf(m, fmaxf(fmaxf(fabsf(v.x), fabsf(v.y)),
                           fmaxf(fabsf(v.z), fabsf(v.w))));
    }
#pragma unroll
    for (int o = 16; o; o >>= 1) m = fmaxf(m, __shfl_xor_sync(0xffffffffu, m, o));
    if ((tid & 31) == 0) red[tid >> 5] = m;
    __syncthreads();
    if (tid == 0) {
        float mm = red[0];
#pragma unroll
        for (int w = 1; w < 8; w++) mm = fmaxf(mm, red[w]);
        // abs values are >= 0, so float bit pattern order == uint order
        atomicMax(out, __float_as_uint(mm));
    }
}

__global__ void __launch_bounds__(256)
qdq_x_kernel(const float* __restrict__ X, float* __restrict__ Xq,
             const unsigned int* __restrict__ amax, size_t n4) {
    float s = __fdiv_rn(__uint_as_float(*amax), 127.0f) + 1e-12f;
    int tid = threadIdx.x;
    size_t i = (size_t)blockIdx.x * blockDim.x + tid;
    size_t stride = (size_t)gridDim.x * blockDim.x;
    const float4* X4 = (const float4*)X;
    float4* O4 = (float4*)Xq;
    for (; i < n4; i += stride) {
        float4 v = X4[i];
        v.x = qdqf(v.x, s); v.y = qdqf(v.y, s);
        v.z = qdqf(v.z, s); v.w = qdqf(v.w, s);
        O4[i] = v;
    }
}

// ---------------------------------------------------------------------------
// TN SGEMM: C[m,n] = sum_k A[m,k]*B[n,k]  (+bias, optional relu, optional qdq)
// Tiles: 128x128x16, 256 threads, 8x8/thread; accumulators held as f32x2
// pairs and updated with fma.rn.f32x2 (FFMA2) => 2x FFMA pipe throughput,
// bitwise-identical per-element accumulation order vs the scalar version.
__global__ void __launch_bounds__(256, 2)
gemm_tn(const float* __restrict__ A, const float* __restrict__ Bw,
        float* __restrict__ C, int lda, int ldb, int ldc, int K,
        const float* __restrict__ bias,
        const float* __restrict__ opsc, int sidx, int relu) {
    __shared__ float As[2][16][128];
    __shared__ float Bs[2][16][128];
    const int tid = threadIdx.x;
    const int tx = tid & 15, ty = tid >> 4;
    const size_t bm = (size_t)blockIdx.y * 128;
    const size_t bn = (size_t)blockIdx.x * 128;

    const int r0 = tid >> 2;                 // 0..63
    const int r1 = (tid + 256) >> 2;         // 64..127
    const int kq = (tid & 3) << 2;           // 0,4,8,12

    const float* Ap0 = A + (bm + r0) * (size_t)lda + kq;
    const float* Ap1 = A + (bm + r1) * (size_t)lda + kq;
    const float* Bp0 = Bw + (bn + r0) * (size_t)ldb + kq;
    const float* Bp1 = Bw + (bn + r1) * (size_t)ldb + kq;

    // acc2[i][0..1] = cols tx*4+{0,1},{2,3};  acc2[i][2..3] = cols 64+tx*4+...
    u64t acc2[8][4];
#pragma unroll
    for (int i = 0; i < 8; i++)
#pragma unroll
        for (int j = 0; j < 4; j++) acc2[i][j] = 0ull;   // {0.0f, 0.0f}

    // prologue: stage chunk 0
    float4 ra0 = *(const float4*)(Ap0);
    float4 ra1 = *(const float4*)(Ap1);
    float4 rb0 = *(const float4*)(Bp0);
    float4 rb1 = *(const float4*)(Bp1);

    const int NC = K >> 4;
    for (int c = 0; c < NC; c++) {
        const int buf = c & 1;
        As[buf][kq + 0][r0] = ra0.x; As[buf][kq + 1][r0] = ra0.y;
        As[buf][kq + 2][r0] = ra0.z; As[buf][kq + 3][r0] = ra0.w;
        As[buf][kq + 0][r1] = ra1.x; As[buf][kq + 1][r1] = ra1.y;
        As[buf][kq + 2][r1] = ra1.z; As[buf][kq + 3][r1] = ra1.w;
        Bs[buf][kq + 0][r0] = rb0.x; Bs[buf][kq + 1][r0] = rb0.y;
        Bs[buf][kq + 2][r0] = rb0.z; Bs[buf][kq + 3][r0] = rb0.w;
        Bs[buf][kq + 0][r1] = rb1.x; Bs[buf][kq + 1][r1] = rb1.y;
        Bs[buf][kq + 2][r1] = rb1.z; Bs[buf][kq + 3][r1] = rb1.w;
        __syncthreads();

        if (c + 1 < NC) {
            const int ko = (c + 1) << 4;
            ra0 = *(const float4*)(Ap0 + ko);
            ra1 = *(const float4*)(Ap1 + ko);
            rb0 = *(const float4*)(Bp0 + ko);
            rb1 = *(const float4*)(Bp1 + ko);
        }

#pragma unroll
        for (int kk = 0; kk < 16; kk++) {
            float a0[4], a1[4], b0[4], b1[4];
            *(float4*)a0 = *(const float4*)&As[buf][kk][ty * 4];
            *(float4*)a1 = *(const float4*)&As[buf][kk][64 + ty * 4];
            *(float4*)b0 = *(const float4*)&Bs[buf][kk][tx * 4];
            *(float4*)b1 = *(const float4*)&Bs[buf][kk][64 + tx * 4];
            u64t B2[4];
            B2[0] = pack2(b0[0], b0[1]); B2[1] = pack2(b0[2], b0[3]);
            B2[2] = pack2(b1[0], b1[1]); B2[3] = pack2(b1[2], b1[3]);
#pragma unroll
            for (int i = 0; i < 8; i++) {
                u64t A2 = bcast2((i < 4) ? a0[i] : a1[i - 4]);
                fma2(acc2[i][0], A2, B2[0]);
                fma2(acc2[i][1], A2, B2[1]);
                fma2(acc2[i][2], A2, B2[2]);
                fma2(acc2[i][3], A2, B2[3]);
            }
        }
    }

    float s = (sidx >= 0) ? opsc[sidx] * 0.05f : 0.0f;
#pragma unroll
    for (int i = 0; i < 8; i++) {
        int r = (i < 4) ? (ty * 4 + i) : (64 + ty * 4 + i - 4);
#pragma unroll
        for (int half = 0; half < 2; half++) {
            int c0 = half * 64 + tx * 4;
            float4 v;
            unpack2(acc2[i][half * 2 + 0], v.x, v.y);
            unpack2(acc2[i][half * 2 + 1], v.z, v.w);
            if (bias) {
                float4 b4 = *(const float4*)(bias + bn + c0);
                v.x += b4.x; v.y += b4.y; v.z += b4.z; v.w += b4.w;
            }
            if (relu) {
                v.x = fmaxf(v.x, 0.0f); v.y = fmaxf(v.y, 0.0f);
                v.z = fmaxf(v.z, 0.0f); v.w = fmaxf(v.w, 0.0f);
            }
            if (sidx >= 0) {
                v.x = qdqf(v.x, s); v.y = qdqf(v.y, s);
                v.z = qdqf(v.z, s); v.w = qdqf(v.w, s);
            }
            *(float4*)(C + (bm + r) * (size_t)ldc + bn + c0) = v;
        }
    }
}

// ---------------------------------------------------------------------------
// Fused flash-style attention (fp32, exact expf, online softmax), with
// f32x2-packed inner products (same per-element IEEE op order as scalar).
#define AT_TQ 128
#define AT_TK 64
#define QS_LD 132   // (AT_TQ + 4)
#define KS_LD 68    // (AT_TK + 4)
#define PS_LD 68

__global__ void __launch_bounds__(256, 2)
attn_fused(const float* __restrict__ Q, const float* __restrict__ K,
           const float* __restrict__ V, float* __restrict__ Ctx) {
    extern __shared__ float sm[];
    float* Qs = sm;                        // [64][QS_LD]  k-major: Qs[kk][r]
    float* Ks = Qs + 64 * QS_LD;           // [64][KS_LD]  k-major: Ks[kk][c]
    float* Vs = Ks + 64 * KS_LD;           // [64][KS_LD]  Vs[kt][d]
    float* Ps = Vs + 64 * KS_LD;           // [128][PS_LD] Ps[r][kt]

    const int tid = threadIdx.x;
    const int tx = tid & 15, ty = tid >> 4;
    const int z = blockIdx.y, b = z >> 4, h = z & 15;
    const size_t bm = (size_t)blockIdx.x * AT_TQ;
    const float* Qg = Q + ((size_t)b * SS) * DD + h * HD;
    const float* Kg = K + ((size_t)b * SS) * DD + h * HD;
    const float* Vg = V + ((size_t)b * SS) * DD + h * HD;

    // Load Q tile (transposed to k-major)
#pragma unroll
    for (int i = 0; i < 8; i++) {
        int idx = tid + i * 256;           // 0..2047
        int r = idx >> 4;                  // 0..127
        int q = (idx & 15) << 2;           // 0..60
        float4 v = *(const float4*)(Qg + (bm + r) * (size_t)DD + q);
        Qs[(q + 0) * QS_LD + r] = v.x; Qs[(q + 1) * QS_LD + r] = v.y;
        Qs[(q + 2) * QS_LD + r] = v.z; Qs[(q + 3) * QS_LD + r] = v.w;
    }

    float m_reg[8], l_reg[8];
    u64t acc2[8][2];     // ctx accumulators: cols tx*4+{0,1},{2,3}
#pragma unroll
    for (int i = 0; i < 8; i++) {
        m_reg[i] = -1e30f; l_reg[i] = 0.0f;
        acc2[i][0] = 0ull; acc2[i][1] = 0ull;
    }

    for (int kt0 = 0; kt0 < SS; kt0 += AT_TK) {
        __syncthreads();   // prev iter done reading Ks/Vs/Ps
#pragma unroll
        for (int i = 0; i < 4; i++) {
            int idx = tid + i * 256;       // 0..1023
            int c = idx >> 4;              // key 0..63
            int q = (idx & 15) << 2;
            float4 kv = *(const float4*)(Kg + (size_t)(kt0 + c) * DD + q);
            Ks[(q + 0) * KS_LD + c] = kv.x; Ks[(q + 1) * KS_LD + c] = kv.y;
            Ks[(q + 2) * KS_LD + c] = kv.z; Ks[(q + 3) * KS_LD + c] = kv.w;
            float4 vv = *(const float4*)(Vg + (size_t)(kt0 + c) * DD + q);
            *(float4*)&Vs[c * KS_LD + q] = vv;
        }
        __syncthreads();

        // S = Q.K^T for this tile (8 rows x 4 cols per thread), f32x2-packed
        u64t s2[8][2];
#pragma unroll
        for (int i = 0; i < 8; i++) { s2[i][0] = 0ull; s2[i][1] = 0ull; }
#pragma unroll 4
        for (int kk = 0; kk < 64; kk++) {
            float a[8], bb[4];
            *(float4*)&a[0] = *(const float4*)&Qs[kk * QS_LD + ty * 8];
            *(float4*)&a[4] = *(const float4*)&Qs[kk * QS_LD + ty * 8 + 4];
            *(float4*)&bb[0] = *(const float4*)&Ks[kk * KS_LD + tx * 4];
            u64t B2[2];
            B2[0] = pack2(bb[0], bb[1]); B2[1] = pack2(bb[2], bb[3]);
#pragma unroll
            for (int i = 0; i < 8; i++) {
                u64t A2 = bcast2(a[i]);
                fma2(s2[i][0], A2, B2[0]);
                fma2(s2[i][1], A2, B2[1]);
            }
        }

        // Online softmax update; write P tile
#pragma unroll
        for (int i = 0; i < 8; i++) {
            float s[4];
            unpack2(s2[i][0], s[0], s[1]);
            unpack2(s2[i][1], s[2], s[3]);
            float mx = fmaxf(fmaxf(s[0], s[1]), fmaxf(s[2], s[3]));
            mx *= 0.125f;
#pragma unroll
            for (int o = 8; o; o >>= 1)
                mx = fmaxf(mx, __shfl_xor_sync(0xffffffffu, mx, o));
            float mn = fmaxf(m_reg[i], mx);
            float alpha = expf(m_reg[i] - mn);
            float4 p4;
            p4.x = expf(s[0] * 0.125f - mn);
            p4.y = expf(s[1] * 0.125f - mn);
            p4.z = expf(s[2] * 0.125f - mn);
            p4.w = expf(s[3] * 0.125f - mn);
            *(float4*)&Ps[(ty * 8 + i) * PS_LD + tx * 4] = p4;
            float ps = (p4.x + p4.y) + (p4.z + p4.w);
#pragma unroll
            for (int o = 8; o; o >>= 1)
                ps += __shfl_xor_sync(0xffffffffu, ps, o);
            l_reg[i] = l_reg[i] * alpha + ps;
            m_reg[i] = mn;
            u64t al2 = bcast2(alpha);
            mul2(acc2[i][0], al2);
            mul2(acc2[i][1], al2);
        }
        __syncthreads();

        // acc += P @ V (f32x2-packed)
#pragma unroll 4
        for (int kt = 0; kt < 64; kt++) {
            float a[8], bb[4];
#pragma unroll
            for (int i = 0; i < 8; i++) a[i] = Ps[(ty * 8 + i) * PS_LD + kt];
            *(float4*)&bb[0] = *(const float4*)&Vs[kt * KS_LD + tx * 4];
            u64t B2[2];
            B2[0] = pack2(bb[0], bb[1]); B2[1] = pack2(bb[2], bb[3]);
#pragma unroll
            for (int i = 0; i < 8; i++) {
                u64t A2 = bcast2(a[i]);
                fma2(acc2[i][0], A2, B2[0]);
                fma2(acc2[i][1], A2, B2[1]);
            }
        }
    }

    // Finalize: divide by row sums, write ctx (layout [b, q, h, d])
    float* Cg = Ctx + ((size_t)b * SS) * DD + h * HD;
#pragma unroll
    for (int i = 0; i < 8; i++) {
        float inv = __fdiv_rn(1.0f, l_reg[i]);
        float4 v;
        unpack2(acc2[i][0], v.x, v.y);
        unpack2(acc2[i][1], v.z, v.w);
        v.x *= inv; v.y *= inv; v.z *= inv; v.w *= inv;
        *(float4*)(Cg + (bm + ty * 8 + i) * (size_t)DD + tx * 4) = v;
    }
}

// ---------------------------------------------------------------------------
// t = qdq(X+Y, s[sa]); Out = qdq(layernorm(t)*w+b, s[sl]). One block per row.
__global__ void __launch_bounds__(256)
add_ln(const float* __restrict__ X, const float* __restrict__ Y,
       const float* __restrict__ w, const float* __restrict__ bvec,
       const float* __restrict__ opsc, int sa, int sl,
       float* __restrict__ Out) {
    __shared__ float red[8];
    const int tid = threadIdx.x;
    const size_t base = (size_t)blockIdx.x * 1024;
    const float s_add = opsc[sa] * 0.05f;
    const float s_ln  = opsc[sl] * 0.05f;
    const int c = tid * 4;
    float4 xv = *(const float4*)(X + base + c);
    float4 yv = *(const float4*)(Y + base + c);
    float v0 = qdqf(xv.x + yv.x, s_add);
    float v1 = qdqf(xv.y + yv.y, s_add);
    float v2 = qdqf(xv.z + yv.z, s_add);
    float v3 = qdqf(xv.w + yv.w, s_add);

    float lsum = (v0 + v1) + (v2 + v3);
#pragma unroll
    for (int o = 16; o; o >>= 1) lsum += __shfl_xor_sync(0xffffffffu, lsum, o);
    if ((tid & 31) == 0) red[tid >> 5] = lsum;
    __syncthreads();
    float tot = 0.0f;
#pragma unroll
    for (int ww = 0; ww < 8; ww++) tot += red[ww];
    float mu = tot * (1.0f / 1024.0f);

    float d0 = v0 - mu, d1 = v1 - mu, d2 = v2 - mu, d3 = v3 - mu;
    float lv = d0 * d0 + d1 * d1 + d2 * d2 + d3 * d3;
#pragma unroll
    for (int o = 16; o; o >>= 1) lv += __shfl_xor_sync(0xffffffffu, lv, o);
    __syncthreads();
    if ((tid & 31) == 0) red[tid >> 5] = lv;
    __syncthreads();
    float vtot = 0.0f;
#pragma unroll
    for (int ww = 0; ww < 8; ww++) vtot += red[ww];
    float var = vtot * (1.0f / 1024.0f);
    float rstd = __fdiv_rn(1.0f, __fsqrt_rn(var + 1e-5f));

    float4 w4 = *(const float4*)(w + c);
    float4 b4 = *(const float4*)(bvec + c);
    float4 o4;
    o4.x = qdqf(d0 * rstd * w4.x + b4.x, s_ln);
    o4.y = qdqf(d1 * rstd * w4.y + b4.y, s_ln);
    o4.z = qdqf(d2 * rstd * w4.z + b4.z, s_ln);
    o4.w = qdqf(d3 * rstd * w4.w + b4.w, s_ln);
    *(float4*)(Out + base + c) = o4;
}

// ---------------------------------------------------------------------------
extern "C" void kernel_launch(void* const* d_in, const int* in_sizes, int n_in,
                              void* d_out, int out_size) {
    const float* x    = (const float*)d_in[0];
    // d_in[1] = attn_mask (all-true for this problem; masking is a no-op)
    const float* wq   = (const float*)d_in[2];
    const float* bq   = (const float*)d_in[3];
    const float* wk   = (const float*)d_in[4];
    const float* bk   = (const float*)d_in[5];
    const float* wv   = (const float*)d_in[6];
    const float* bv   = (const float*)d_in[7];
    const float* wo   = (const float*)d_in[8];
    const float* bo   = (const float*)d_in[9];
    const float* w1   = (const float*)d_in[10];
    const float* b1   = (const float*)d_in[11];
    const float* w2   = (const float*)d_in[12];
    const float* b2   = (const float*)d_in[13];
    const float* ln1w = (const float*)d_in[14];
    const float* ln1b = (const float*)d_in[15];
    const float* ln2w = (const float*)d_in[16];
    const float* ln2b = (const float*)d_in[17];
    const float* opsc = (const float*)d_in[18];
    float* out = (float*)d_out;

    float *xq, *q, *k, *v, *ctx, *o, *h, *f, *f2;
    unsigned int* amax;
    cudaGetSymbolAddress((void**)&xq,  g_xq);
    cudaGetSymbolAddress((void**)&q,   g_q);
    cudaGetSymbolAddress((void**)&k,   g_k);
    cudaGetSymbolAddress((void**)&v,   g_v);
    cudaGetSymbolAddress((void**)&ctx, g_ctx);
    cudaGetSymbolAddress((void**)&o,   g_o);
    cudaGetSymbolAddress((void**)&h,   g_h);
    cudaGetSymbolAddress((void**)&f,   g_f);
    cudaGetSymbolAddress((void**)&f2,  g_f2);
    cudaGetSymbolAddress((void**)&amax, g_amax);

    // fused attention needs > 48 KB dynamic smem
    static const int ATT_SMEM = (64 * QS_LD + 64 * KS_LD + 64 * KS_LD + 128 * PS_LD) * 4;
    cudaFuncSetAttribute(attn_fused, cudaFuncAttributeMaxDynamicSharedMemorySize, ATT_SMEM);

    init_amax_kernel<<<1, 32>>>();

    // input quantization (dynamic per-tensor scale)
    absmax_kernel<<<1024, 256>>>(x, NX / 4, amax + 0);
    qdq_x_kernel<<<2048, 256>>>(x, xq, amax + 0, NX / 4);

    // QKV projections (note reference wiring: k <- (wv,bv), v <- (wk,bk))
    dim3 g64(8, 64);
    gemm_tn<<<g64, 256>>>(xq, wq, q, DD, DD, DD, DD, bq, opsc, 0, 0);
    gemm_tn<<<g64, 256>>>(xq, wv, k, DD, DD, DD, DD, bv, opsc, 1, 0);
    gemm_tn<<<g64, 256>>>(xq, wk, v, DD, DD, DD, DD, bk, opsc, 2, 0);

    // fused attention (scores + softmax + ctx), no materialized score tensor
    attn_fused<<<dim3(SS / AT_TQ, BB * HH), 256, ATT_SMEM>>>(q, k, v, ctx);

    // requantize ctx with dynamic scale (elementwise, into free q buffer),
    // then O projection
    absmax_kernel<<<1024, 256>>>(ctx, NX / 4, amax + 1);
    qdq_x_kernel<<<2048, 256>>>(ctx, q, amax + 1, NX / 4);
    gemm_tn<<<g64, 256>>>(q, wo, o, DD, DD, DD, DD, bo, opsc, 3, 0);

    // residual + LN1
    add_ln<<<BB * SS, 256>>>(xq, o, ln1w, ln1b, opsc, 8, 6, h);

    // FFN
    gemm_tn<<<dim3(32, 64), 256>>>(h, w1, f,  DD, DD, FF, DD, b1, opsc, 4, 1);
    gemm_tn<<<dim3(8, 64), 256>>>(f, w2, f2, FF, FF, DD, FF, b2, opsc, 5, 0);

    // residual + LN2 -> output
    add_ln<<<BB * SS, 256>>>(h, f2, ln2w, ln2b, opsc, 9, 7, out);
}

// round 15
// speedup vs baseline: 1.2070x; 1.1411x over previous
#include <cuda_runtime.h>
#include <cuda_bf16.h>
#include <math.h>
#include <stdint.h>
#include <stddef.h>

// Problem dims (fixed)
#define BB 4
#define SS 2048
#define DD 1024
#define HH 16
#define HD 64
#define FF 4096

static const size_t NX = (size_t)BB * SS * DD;        // 8388608

// ---------------------------------------------------------------------------
// Scratch (device globals; allocation APIs are forbidden)
__device__ float g_xq [8388608];
__device__ float g_q  [8388608];
__device__ float g_k  [8388608];
__device__ float g_v  [8388608];
__device__ float g_ctx[8388608];
__device__ float g_o  [8388608];
__device__ float g_h  [8388608];
__device__ float g_f  [33554432];
__device__ float g_f2 [8388608];
__device__ unsigned char g_fu [33554432];   // u8 codes of f (FFN2 IMMA input)
__device__ signed char g_w24[4 * 4194304];
__device__ float g_cs2[1024];
// amax slots: 0=x, 1=ctx, 7=w2
__device__ unsigned int g_amax[8];

// ---------------------------------------------------------------------------
// Packed f32x2 helpers
typedef unsigned long long u64t;
__device__ __forceinline__ u64t pack2(float x, float y) {
    u64t r; asm("mov.b64 %0, {%1, %2};" : "=l"(r) : "f"(x), "f"(y)); return r;
}
__device__ __forceinline__ u64t bcast2(float x) {
    u64t r; asm("mov.b64 %0, {%1, %1};" : "=l"(r) : "f"(x)); return r;
}
__device__ __forceinline__ void fma2(u64t& a, u64t b, u64t c) {
    asm("fma.rn.f32x2 %0, %1, %2, %0;" : "+l"(a) : "l"(b), "l"(c));
}
__device__ __forceinline__ void mul2(u64t& a, u64t s) {
    asm("mul.rn.f32x2 %0, %0, %1;" : "+l"(a) : "l"(s));
}
__device__ __forceinline__ void unpack2(u64t v, float& x, float& y) {
    asm("mov.b64 {%0, %1}, %2;" : "=f"(x), "=f"(y) : "l"(v));
}

// ---------------------------------------------------------------------------
// compute_100-safe tensor-core / async-copy primitives (FFN2 IMMA path)
__device__ __forceinline__ uint32_t smem_u32(const void* p) {
    uint32_t a;
    asm("{ .reg .u64 t; cvta.to.shared.u64 t, %1; cvt.u32.u64 %0, t; }"
        : "=r"(a) : "l"(p));
    return a;
}
__device__ __forceinline__ void cp_async16(uint32_t saddr, const void* gaddr) {
    asm volatile("cp.async.ca.shared.global [%0], [%1], 16;"
                 :: "r"(saddr), "l"(gaddr) : "memory");
}
#define CP_COMMIT() asm volatile("cp.async.commit_group;" ::: "memory")
#define CP_WAIT1()  asm volatile("cp.async.wait_group 1;" ::: "memory")
#define CP_WAIT0()  asm volatile("cp.async.wait_group 0;" ::: "memory")

__device__ __forceinline__ void ldsm4(uint32_t* r, uint32_t a) {
    asm volatile("ldmatrix.sync.aligned.m8n8.x4.shared.b16 {%0,%1,%2,%3}, [%4];"
                 : "=r"(r[0]), "=r"(r[1]), "=r"(r[2]), "=r"(r[3]) : "r"(a));
}
// Integer MMA: u8 A, s8 B, s32 accumulate (chained). Bit-exact.
__device__ __forceinline__ void imma16832(int* c, const uint32_t* a,
                                          uint32_t b0, uint32_t b1) {
    asm volatile("mma.sync.aligned.m16n8k32.row.col.s32.u8.s8.s32 "
                 "{%0,%1,%2,%3}, {%4,%5,%6,%7}, {%8,%9}, {%0,%1,%2,%3};"
                 : "+r"(c[0]), "+r"(c[1]), "+r"(c[2]), "+r"(c[3])
                 : "r"(a[0]), "r"(a[1]), "r"(a[2]), "r"(a[3]), "r"(b0), "r"(b1));
}

// ---------------------------------------------------------------------------
// qdq matching the JAX fp32 reference (IEEE div, round-half-even)
__device__ __forceinline__ float qdqf(float x, float s) {
    float r = rintf(__fdiv_rn(x, s));
    r = fminf(fmaxf(r + 64.0f, 0.0f), 255.0f);
    return (r - 64.0f) * s;
}

// ---------------------------------------------------------------------------
__global__ void __launch_bounds__(32)
init_amax_kernel() {
    if (threadIdx.x < 8) g_amax[threadIdx.x] = 0u;
}

__global__ void __launch_bounds__(256)
absmax_kernel(const float* __restrict__ X, size_t n4, unsigned int* __restrict__ out) {
    __shared__ float red[8];
    int tid = threadIdx.x;
    size_t i = (size_t)blockIdx.x * blockDim.x + tid;
    size_t stride = (size_t)gridDim.x * blockDim.x;
    const float4* X4 = (const float4*)X;
    float m = 0.0f;
    for (; i < n4; i += stride) {
        float4 v = X4[i];
        m = fmaxf(m, fmaxf(fmaxf(fabsf(v.x), fabsf(v.y)),
                           fmaxf(fabsf(v.z), fabsf(v.w))));
    }
#pragma unroll
    for (int o = 16; o; o >>= 1) m = fmaxf(m, __shfl_xor_sync(0xffffffffu, m, o));
    if ((tid & 31) == 0) red[tid >> 5] = m;
    __syncthreads();
    if (tid == 0) {
        float mm = red[0];
#pragma unroll
        for (int w = 1; w < 8; w++) mm = fmaxf(mm, red[w]);
        atomicMax(out, __float_as_uint(mm));
    }
}

// R5 qdq (fp32 out only) — bitwise identical to the passing kernel
__global__ void __launch_bounds__(256)
qdq_x_kernel(const float* __restrict__ X, float* __restrict__ Xq,
             const unsigned int* __restrict__ amax, size_t n4) {
    float s = __fdiv_rn(__uint_as_float(*amax), 127.0f) + 1e-12f;
    int tid = threadIdx.x;
    size_t i = (size_t)blockIdx.x * blockDim.x + tid;
    size_t stride = (size_t)gridDim.x * blockDim.x;
    const float4* X4 = (const float4*)X;
    float4* O4 = (float4*)Xq;
    for (; i < n4; i += stride) {
        float4 v = X4[i];
        v.x = qdqf(v.x, s); v.y = qdqf(v.y, s);
        v.z = qdqf(v.z, s); v.w = qdqf(v.w, s);
        O4[i] = v;
    }
}

// 4-level 7-bit integer split: W = S1 w1 + S2 w2 + S3 w3 + S4 w4 + rho,
// Si = 2^(ev-6-7(i-1)), wi integer in [-64,64] (s8-safe), |rho| <= 2^(ev-28).
__global__ void __launch_bounds__(256)
split_w8_kernel(const float* __restrict__ W, signed char* __restrict__ S, int n,
                const unsigned int* __restrict__ wmaxp) {
    float wmx = __uint_as_float(*wmaxp);
    int ev;
    frexpf(wmx, &ev);
    float S1 = exp2f((float)(ev - 6)),  I1 = exp2f((float)(6 - ev));
    float S2 = exp2f((float)(ev - 13)), I2 = exp2f((float)(13 - ev));
    float S3 = exp2f((float)(ev - 20)), I3 = exp2f((float)(20 - ev));
    float I4 = exp2f((float)(27 - ev));
    int i = blockIdx.x * blockDim.x + threadIdx.x;
    int stride = gridDim.x * blockDim.x;
    for (; i < n; i += stride) {
        float w = W[i];
        float w1 = rintf(w * I1);  float r1 = fmaf(-w1, S1, w);
        float w2 = rintf(r1 * I2); float r2 = fmaf(-w2, S2, r1);
        float w3 = rintf(r2 * I3); float r3 = fmaf(-w3, S3, r2);
        float w4 = rintf(r3 * I4);
        S[i]         = (signed char)__float2int_rn(w1);
        S[n + i]     = (signed char)__float2int_rn(w2);
        S[2 * n + i] = (signed char)__float2int_rn(w3);
        S[3 * n + i] = (signed char)__float2int_rn(w4);
    }
}

// csum[j] = sum_sp S_sp * (integer rowsum of w_sp[j,:])  (zero-point term)
__global__ void __launch_bounds__(256)
rowsum_kernel(const signed char* __restrict__ S, int N, int K,
              const unsigned int* __restrict__ wmaxp, float* __restrict__ csum) {
    __shared__ int red[4][8];
    int j = blockIdx.x, tid = threadIdx.x;
    const size_t sps = (size_t)N * K;
    const signed char* r0 = S + (size_t)j * K;
    int acc[4] = {0, 0, 0, 0};
    for (int k = tid * 4; k < K; k += 1024) {
#pragma unroll
        for (int sp = 0; sp < 4; sp++)
            acc[sp] = __dp4a(*(const int*)(r0 + sp * sps + k), 0x01010101, acc[sp]);
    }
#pragma unroll
    for (int sp = 0; sp < 4; sp++) {
#pragma unroll
        for (int o = 16; o; o >>= 1)
            acc[sp] += __shfl_xor_sync(0xffffffffu, acc[sp], o);
        if ((tid & 31) == 0) red[sp][tid >> 5] = acc[sp];
    }
    __syncthreads();
    if (tid == 0) {
        float wmx = __uint_as_float(*wmaxp);
        int ev;
        frexpf(wmx, &ev);
        float t = 0.0f;
#pragma unroll
        for (int sp = 0; sp < 4; sp++) {
            int s = 0;
#pragma unroll
            for (int w = 0; w < 8; w++) s += red[sp][w];
            t = fmaf(exp2f((float)(ev - 6 - 7 * sp)), (float)s, t);
        }
        csum[j] = t;
    }
}

// ---------------------------------------------------------------------------
// R5 TN SGEMM (f32x2, double-buffered) — fp32 path bitwise identical to the
// passing kernel. Optional u8-code output (the q value qdq already computes).
// Used for QKV, O, FFN1.
__global__ void __launch_bounds__(256, 2)
gemm_tn(const float* __restrict__ A, const float* __restrict__ Bw,
        float* __restrict__ C, int lda, int ldb, int ldc, int K,
        const float* __restrict__ bias,
        const float* __restrict__ opsc, int sidx, int relu,
        unsigned char* __restrict__ Cu) {
    __shared__ float As[2][16][128];
    __shared__ float Bs[2][16][128];
    const int tid = threadIdx.x;
    const int tx = tid & 15, ty = tid >> 4;
    const size_t bm = (size_t)blockIdx.y * 128;
    const size_t bn = (size_t)blockIdx.x * 128;

    const int r0 = tid >> 2;
    const int r1 = (tid + 256) >> 2;
    const int kq = (tid & 3) << 2;

    const float* Ap0 = A + (bm + r0) * (size_t)lda + kq;
    const float* Ap1 = A + (bm + r1) * (size_t)lda + kq;
    const float* Bp0 = Bw + (bn + r0) * (size_t)ldb + kq;
    const float* Bp1 = Bw + (bn + r1) * (size_t)ldb + kq;

    u64t acc2[8][4];
#pragma unroll
    for (int i = 0; i < 8; i++)
#pragma unroll
        for (int j = 0; j < 4; j++) acc2[i][j] = 0ull;

    float4 ra0 = *(const float4*)(Ap0);
    float4 ra1 = *(const float4*)(Ap1);
    float4 rb0 = *(const float4*)(Bp0);
    float4 rb1 = *(const float4*)(Bp1);

    const int NC = K >> 4;
    for (int c = 0; c < NC; c++) {
        const int buf = c & 1;
        As[buf][kq + 0][r0] = ra0.x; As[buf][kq + 1][r0] = ra0.y;
        As[buf][kq + 2][r0] = ra0.z; As[buf][kq + 3][r0] = ra0.w;
        As[buf][kq + 0][r1] = ra1.x; As[buf][kq + 1][r1] = ra1.y;
        As[buf][kq + 2][r1] = ra1.z; As[buf][kq + 3][r1] = ra1.w;
        Bs[buf][kq + 0][r0] = rb0.x; Bs[buf][kq + 1][r0] = rb0.y;
        Bs[buf][kq + 2][r0] = rb0.z; Bs[buf][kq + 3][r0] = rb0.w;
        Bs[buf][kq + 0][r1] = rb1.x; Bs[buf][kq + 1][r1] = rb1.y;
        Bs[buf][kq + 2][r1] = rb1.z; Bs[buf][kq + 3][r1] = rb1.w;
        __syncthreads();

        if (c + 1 < NC) {
            const int ko = (c + 1) << 4;
            ra0 = *(const float4*)(Ap0 + ko);
            ra1 = *(const float4*)(Ap1 + ko);
            rb0 = *(const float4*)(Bp0 + ko);
            rb1 = *(const float4*)(Bp1 + ko);
        }

#pragma unroll
        for (int kk = 0; kk < 16; kk++) {
            float a0[4], a1[4], b0[4], b1[4];
            *(float4*)a0 = *(const float4*)&As[buf][kk][ty * 4];
            *(float4*)a1 = *(const float4*)&As[buf][kk][64 + ty * 4];
            *(float4*)b0 = *(const float4*)&Bs[buf][kk][tx * 4];
            *(float4*)b1 = *(const float4*)&Bs[buf][kk][64 + tx * 4];
            u64t B2[4];
            B2[0] = pack2(b0[0], b0[1]); B2[1] = pack2(b0[2], b0[3]);
            B2[2] = pack2(b1[0], b1[1]); B2[3] = pack2(b1[2], b1[3]);
#pragma unroll
            for (int i = 0; i < 8; i++) {
                u64t A2 = bcast2((i < 4) ? a0[i] : a1[i - 4]);
                fma2(acc2[i][0], A2, B2[0]);
                fma2(acc2[i][1], A2, B2[1]);
                fma2(acc2[i][2], A2, B2[2]);
                fma2(acc2[i][3], A2, B2[3]);
            }
        }
    }

    float s = (sidx >= 0) ? opsc[sidx] * 0.05f : 0.0f;
#pragma unroll
    for (int i = 0; i < 8; i++) {
        int r = (i < 4) ? (ty * 4 + i) : (64 + ty * 4 + i - 4);
#pragma unroll
        for (int half = 0; half < 2; half++) {
            int c0 = half * 64 + tx * 4;
            float4 v;
            unpack2(acc2[i][half * 2 + 0], v.x, v.y);
            unpack2(acc2[i][half * 2 + 1], v.z, v.w);
            if (bias) {
                float4 b4 = *(const float4*)(bias + bn + c0);
                v.x += b4.x; v.y += b4.y; v.z += b4.z; v.w += b4.w;
            }
            if (relu) {
                v.x = fmaxf(v.x, 0.0f); v.y = fmaxf(v.y, 0.0f);
                v.z = fmaxf(v.z, 0.0f); v.w = fmaxf(v.w, 0.0f);
            }
            size_t g = (bm + r) * (size_t)ldc + bn + c0;
            if (sidx >= 0) {
                // inline qdq, identical op sequence to qdqf; also yields codes
                float q0 = fminf(fmaxf(rintf(__fdiv_rn(v.x, s)) + 64.0f, 0.0f), 255.0f);
                float q1 = fminf(fmaxf(rintf(__fdiv_rn(v.y, s)) + 64.0f, 0.0f), 255.0f);
                float q2 = fminf(fmaxf(rintf(__fdiv_rn(v.z, s)) + 64.0f, 0.0f), 255.0f);
                float q3 = fminf(fmaxf(rintf(__fdiv_rn(v.w, s)) + 64.0f, 0.0f), 255.0f);
                v.x = (q0 - 64.0f) * s; v.y = (q1 - 64.0f) * s;
                v.z = (q2 - 64.0f) * s; v.w = (q3 - 64.0f) * s;
                if (Cu) {
                    uchar4 u;
                    u.x = (unsigned char)q0; u.y = (unsigned char)q1;
                    u.z = (unsigned char)q2; u.w = (unsigned char)q3;
                    *(uchar4*)(Cu + g) = u;
                }
            }
            *(float4*)(C + g) = v;
        }
    }
}

// ---------------------------------------------------------------------------
// Integer tensor-core TN GEMM (u8 x s8 -> s32) — FFN2 (K=4096), R12 config:
// raw s32 chained over 16-chunk (1024-k) groups, fp32 fold per split group,
// zero-point (64*csum) subtracted in fp32 epilogue.
#define G8_STRIDE 80
#define G8_TILE   10240
#define G8_BUF    20480
#define G8_TOTAL  40960

__global__ void __launch_bounds__(256)
gemm_imma(const unsigned char* __restrict__ Aq,
          const signed char* __restrict__ Bsplit,
          int N, int K,
          const float* __restrict__ bias,
          const float* __restrict__ csum,
          const unsigned int* __restrict__ wmaxp,
          const float* __restrict__ opsc, int a_sidx, int out_sidx,
          int relu,
          float* __restrict__ Cf) {
    extern __shared__ unsigned char dynsm[];
    const uint32_t s0 = smem_u32(dynsm);

    const int tid = threadIdx.x;
    const int wid = tid >> 5;
    const int lane = tid & 31;
    const int wm = wid & 3;
    const int wn = wid >> 2;

    const size_t bm = (size_t)blockIdx.y * 128;
    const size_t bn = (size_t)blockIdx.x * 128;
    const unsigned char* Ag = Aq + bm * (size_t)K;
    const size_t spstride = (size_t)N * K;

    const int kc = K >> 6;           // 64 for K=4096
    const int NCT = 4 * kc;          // 256

    float wmx = __uint_as_float(*wmaxp);
    int ev;
    frexpf(wmx, &ev);
    float Ss[4];
#pragma unroll
    for (int sp = 0; sp < 4; sp++) Ss[sp] = exp2f((float)(ev - 6 - 7 * sp));

    int acc_i[2][8][4];
    float acc_f[2][8][4];
#pragma unroll
    for (int mt = 0; mt < 2; mt++)
#pragma unroll
        for (int nt = 0; nt < 8; nt++)
#pragma unroll
            for (int r = 0; r < 4; r++) { acc_i[mt][nt][r] = 0; acc_f[mt][nt][r] = 0.0f; }

    auto load_chunk = [&](int c, int bufsel) {
        int sp = c / kc;
        int kk = (c - sp * kc) << 6;
        const signed char* Bg = Bsplit + (size_t)sp * spstride + bn * (size_t)K;
        uint32_t sa = s0 + bufsel * G8_BUF;
        uint32_t sb = sa + G8_TILE;
#pragma unroll
        for (int j = 0; j < 2; j++) {
            int lin = tid + j * 256;
            int row = lin >> 2;
            int cb = (lin & 3) * 16;
            cp_async16(sa + row * G8_STRIDE + cb, Ag + (size_t)row * K + kk + cb);
            cp_async16(sb + row * G8_STRIDE + cb, Bg + (size_t)row * K + kk + cb);
        }
        CP_COMMIT();
    };

    load_chunk(0, 0);
    if (NCT > 1) load_chunk(1, 1);

    for (int c = 0; c < NCT; c++) {
        if (c + 1 < NCT) { CP_WAIT1(); } else { CP_WAIT0(); }
        __syncthreads();

        uint32_t sa = s0 + (c & 1) * G8_BUF;
        uint32_t sb = sa + G8_TILE;
        uint32_t a_base = sa + (wm * 32 + (lane & 15)) * G8_STRIDE + ((lane >> 4) * 16);
        uint32_t b_base = sb + (wn * 64 + (lane & 15)) * G8_STRIDE + ((lane >> 4) * 16);

#pragma unroll
        for (int ks = 0; ks < 2; ks++) {
            uint32_t ra[2][4];
            ldsm4(ra[0], a_base + ks * 32);
            ldsm4(ra[1], a_base + 16 * G8_STRIDE + ks * 32);
#pragma unroll
            for (int ng = 0; ng < 4; ng++) {
                uint32_t rb[4];
                ldsm4(rb, b_base + ng * 16 * G8_STRIDE + ks * 32);
                imma16832(acc_i[0][2 * ng],     ra[0], rb[0], rb[2]);
                imma16832(acc_i[0][2 * ng + 1], ra[0], rb[1], rb[3]);
                imma16832(acc_i[1][2 * ng],     ra[1], rb[0], rb[2]);
                imma16832(acc_i[1][2 * ng + 1], ra[1], rb[1], rb[3]);
            }
        }

        // fold s32 -> fp32 every 16 chunks (1024 k): |acc_i| < 2^24 => exact cvt
        if (((c + 1) & 15) == 0) {
            float Scur = Ss[c / kc];
#pragma unroll
            for (int mt = 0; mt < 2; mt++)
#pragma unroll
                for (int nt = 0; nt < 8; nt++)
#pragma unroll
                    for (int r = 0; r < 4; r++) {
                        acc_f[mt][nt][r] = fmaf(Scur, (float)acc_i[mt][nt][r],
                                                acc_f[mt][nt][r]);
                        acc_i[mt][nt][r] = 0;
                    }
        }

        __syncthreads();
        if (c + 2 < NCT) load_chunk(c + 2, c & 1);
    }

    float s_a = opsc[a_sidx] * 0.05f;
    float s_out = opsc[out_sidx] * 0.05f;

#pragma unroll
    for (int mt = 0; mt < 2; mt++) {
        size_t m0 = bm + wm * 32 + mt * 16 + (lane >> 2);
#pragma unroll
        for (int nt = 0; nt < 8; nt++) {
            int n0 = (int)bn + wn * 64 + nt * 8 + (lane & 3) * 2;
            float b0v = bias[n0], b1v = bias[n0 + 1];
            float c0v = csum[n0], c1v = csum[n0 + 1];
            float t0 = fmaf(-64.0f, c0v, acc_f[mt][nt][0]);
            float t1 = fmaf(-64.0f, c1v, acc_f[mt][nt][1]);
            float t2 = fmaf(-64.0f, c0v, acc_f[mt][nt][2]);
            float t3 = fmaf(-64.0f, c1v, acc_f[mt][nt][3]);
            float y0 = fmaf(t0, s_a, b0v);
            float y1 = fmaf(t1, s_a, b1v);
            float y2 = fmaf(t2, s_a, b0v);
            float y3 = fmaf(t3, s_a, b1v);
            if (relu) {
                y0 = fmaxf(y0, 0.0f); y1 = fmaxf(y1, 0.0f);
                y2 = fmaxf(y2, 0.0f); y3 = fmaxf(y3, 0.0f);
            }
            float qv0 = fminf(fmaxf(rintf(__fdiv_rn(y0, s_out)) + 64.0f, 0.0f), 255.0f);
            float qv1 = fminf(fmaxf(rintf(__fdiv_rn(y1, s_out)) + 64.0f, 0.0f), 255.0f);
            float qv2 = fminf(fmaxf(rintf(__fdiv_rn(y2, s_out)) + 64.0f, 0.0f), 255.0f);
            float qv3 = fminf(fmaxf(rintf(__fdiv_rn(y3, s_out)) + 64.0f, 0.0f), 255.0f);
            size_t g0 = m0 * (size_t)N + n0;
            size_t g1 = g0 + 8 * (size_t)N;
            float2 o01; o01.x = (qv0 - 64.0f) * s_out; o01.y = (qv1 - 64.0f) * s_out;
            float2 o23; o23.x = (qv2 - 64.0f) * s_out; o23.y = (qv3 - 64.0f) * s_out;
            *(float2*)(Cf + g0) = o01;
            *(float2*)(Cf + g1) = o23;
        }
    }
}

// ---------------------------------------------------------------------------
// Fused flash-style attention — bitwise identical to the R5 passing kernel.
#define AT_TQ 128
#define AT_TK 64
#define QS_LD 132
#define KS_LD 68
#define PS_LD 68

__global__ void __launch_bounds__(256, 2)
attn_fused(const float* __restrict__ Q, const float* __restrict__ K,
           const float* __restrict__ V, float* __restrict__ Ctx) {
    extern __shared__ float sm[];
    float* Qs = sm;
    float* Ks = Qs + 64 * QS_LD;
    float* Vs = Ks + 64 * KS_LD;
    float* Ps = Vs + 64 * KS_LD;

    const int tid = threadIdx.x;
    const int tx = tid & 15, ty = tid >> 4;
    const int z = blockIdx.y, b = z >> 4, h = z & 15;
    const size_t bm = (size_t)blockIdx.x * AT_TQ;
    const float* Qg = Q + ((size_t)b * SS) * DD + h * HD;
    const float* Kg = K + ((size_t)b * SS) * DD + h * HD;
    const float* Vg = V + ((size_t)b * SS) * DD + h * HD;

#pragma unroll
    for (int i = 0; i < 8; i++) {
        int idx = tid + i * 256;
        int r = idx >> 4;
        int q = (idx & 15) << 2;
        float4 v = *(const float4*)(Qg + (bm + r) * (size_t)DD + q);
        Qs[(q + 0) * QS_LD + r] = v.x; Qs[(q + 1) * QS_LD + r] = v.y;
        Qs[(q + 2) * QS_LD + r] = v.z; Qs[(q + 3) * QS_LD + r] = v.w;
    }

    float m_reg[8], l_reg[8];
    u64t acc2[8][2];
#pragma unroll
    for (int i = 0; i < 8; i++) {
        m_reg[i] = -1e30f; l_reg[i] = 0.0f;
        acc2[i][0] = 0ull; acc2[i][1] = 0ull;
    }

    for (int kt0 = 0; kt0 < SS; kt0 += AT_TK) {
        __syncthreads();
#pragma unroll
        for (int i = 0; i < 4; i++) {
            int idx = tid + i * 256;
            int c = idx >> 4;
            int q = (idx & 15) << 2;
            float4 kv = *(const float4*)(Kg + (size_t)(kt0 + c) * DD + q);
            Ks[(q + 0) * KS_LD + c] = kv.x; Ks[(q + 1) * KS_LD + c] = kv.y;
            Ks[(q + 2) * KS_LD + c] = kv.z; Ks[(q + 3) * KS_LD + c] = kv.w;
            float4 vv = *(const float4*)(Vg + (size_t)(kt0 + c) * DD + q);
            *(float4*)&Vs[c * KS_LD + q] = vv;
        }
        __syncthreads();

        u64t s2[8][2];
#pragma unroll
        for (int i = 0; i < 8; i++) { s2[i][0] = 0ull; s2[i][1] = 0ull; }
#pragma unroll 4
        for (int kk = 0; kk < 64; kk++) {
            float a[8], bb[4];
            *(float4*)&a[0] = *(const float4*)&Qs[kk * QS_LD + ty * 8];
            *(float4*)&a[4] = *(const float4*)&Qs[kk * QS_LD + ty * 8 + 4];
            *(float4*)&bb[0] = *(const float4*)&Ks[kk * KS_LD + tx * 4];
            u64t B2[2];
            B2[0] = pack2(bb[0], bb[1]); B2[1] = pack2(bb[2], bb[3]);
#pragma unroll
            for (int i = 0; i < 8; i++) {
                u64t A2 = bcast2(a[i]);
                fma2(s2[i][0], A2, B2[0]);
                fma2(s2[i][1], A2, B2[1]);
            }
        }

#pragma unroll
        for (int i = 0; i < 8; i++) {
            float s[4];
            unpack2(s2[i][0], s[0], s[1]);
            unpack2(s2[i][1], s[2], s[3]);
            float mx = fmaxf(fmaxf(s[0], s[1]), fmaxf(s[2], s[3]));
            mx *= 0.125f;
#pragma unroll
            for (int o = 8; o; o >>= 1)
                mx = fmaxf(mx, __shfl_xor_sync(0xffffffffu, mx, o));
            float mn = fmaxf(m_reg[i], mx);
            float alpha = expf(m_reg[i] - mn);
            float4 p4;
            p4.x = expf(s[0] * 0.125f - mn);
            p4.y = expf(s[1] * 0.125f - mn);
            p4.z = expf(s[2] * 0.125f - mn);
            p4.w = expf(s[3] * 0.125f - mn);
            *(float4*)&Ps[(ty * 8 + i) * PS_LD + tx * 4] = p4;
            float ps = (p4.x + p4.y) + (p4.z + p4.w);
#pragma unroll
            for (int o = 8; o; o >>= 1)
                ps += __shfl_xor_sync(0xffffffffu, ps, o);
            l_reg[i] = l_reg[i] * alpha + ps;
            m_reg[i] = mn;
            u64t al2 = bcast2(alpha);
            mul2(acc2[i][0], al2);
            mul2(acc2[i][1], al2);
        }
        __syncthreads();

#pragma unroll 4
        for (int kt = 0; kt < 64; kt++) {
            float a[8], bb[4];
#pragma unroll
            for (int i = 0; i < 8; i++) a[i] = Ps[(ty * 8 + i) * PS_LD + kt];
            *(float4*)&bb[0] = *(const float4*)&Vs[kt * KS_LD + tx * 4];
            u64t B2[2];
            B2[0] = pack2(bb[0], bb[1]); B2[1] = pack2(bb[2], bb[3]);
#pragma unroll
            for (int i = 0; i < 8; i++) {
                u64t A2 = bcast2(a[i]);
                fma2(acc2[i][0], A2, B2[0]);
                fma2(acc2[i][1], A2, B2[1]);
            }
        }
    }

    float* Cg = Ctx + ((size_t)b * SS) * DD + h * HD;
#pragma unroll
    for (int i = 0; i < 8; i++) {
        float inv = __fdiv_rn(1.0f, l_reg[i]);
        float4 v;
        unpack2(acc2[i][0], v.x, v.y);
        unpack2(acc2[i][1], v.z, v.w);
        v.x *= inv; v.y *= inv; v.z *= inv; v.w *= inv;
        *(float4*)(Cg + (bm + ty * 8 + i) * (size_t)DD + tx * 4) = v;
    }
}

// ---------------------------------------------------------------------------
// t = qdq(X+Y, s[sa]); Out = qdq(layernorm(t)*w+b, s[sl]).  Bitwise R5 path.
__global__ void __launch_bounds__(256)
add_ln(const float* __restrict__ X, const float* __restrict__ Y,
       const float* __restrict__ w, const float* __restrict__ bvec,
       const float* __restrict__ opsc, int sa, int sl,
       float* __restrict__ Out) {
    __shared__ float red[8];
    const int tid = threadIdx.x;
    const size_t base = (size_t)blockIdx.x * 1024;
    const float s_add = opsc[sa] * 0.05f;
    const float s_ln  = opsc[sl] * 0.05f;
    const int c = tid * 4;
    float4 xv = *(const float4*)(X + base + c);
    float4 yv = *(const float4*)(Y + base + c);
    float v0 = qdqf(xv.x + yv.x, s_add);
    float v1 = qdqf(xv.y + yv.y, s_add);
    float v2 = qdqf(xv.z + yv.z, s_add);
    float v3 = qdqf(xv.w + yv.w, s_add);

    float lsum = (v0 + v1) + (v2 + v3);
#pragma unroll
    for (int o = 16; o; o >>= 1) lsum += __shfl_xor_sync(0xffffffffu, lsum, o);
    if ((tid & 31) == 0) red[tid >> 5] = lsum;
    __syncthreads();
    float tot = 0.0f;
#pragma unroll
    for (int ww = 0; ww < 8; ww++) tot += red[ww];
    float mu = tot * (1.0f / 1024.0f);

    float d0 = v0 - mu, d1 = v1 - mu, d2 = v2 - mu, d3 = v3 - mu;
    float lv = d0 * d0 + d1 * d1 + d2 * d2 + d3 * d3;
#pragma unroll
    for (int o = 16; o; o >>= 1) lv += __shfl_xor_sync(0xffffffffu, lv, o);
    __syncthreads();
    if ((tid & 31) == 0) red[tid >> 5] = lv;
    __syncthreads();
    float vtot = 0.0f;
#pragma unroll
    for (int ww = 0; ww < 8; ww++) vtot += red[ww];
    float var = vtot * (1.0f / 1024.0f);
    float rstd = __fdiv_rn(1.0f, __fsqrt_rn(var + 1e-5f));

    float4 w4 = *(const float4*)(w + c);
    float4 b4 = *(const float4*)(bvec + c);
    float4 o4;
    o4.x = qdqf(d0 * rstd * w4.x + b4.x, s_ln);
    o4.y = qdqf(d1 * rstd * w4.y + b4.y, s_ln);
    o4.z = qdqf(d2 * rstd * w4.z + b4.z, s_ln);
    o4.w = qdqf(d3 * rstd * w4.w + b4.w, s_ln);
    *(float4*)(Out + base + c) = o4;
}

// ---------------------------------------------------------------------------
extern "C" void kernel_launch(void* const* d_in, const int* in_sizes, int n_in,
                              void* d_out, int out_size) {
    const float* x    = (const float*)d_in[0];
    const float* wq   = (const float*)d_in[2];
    const float* bq   = (const float*)d_in[3];
    const float* wk   = (const float*)d_in[4];
    const float* bk   = (const float*)d_in[5];
    const float* wv   = (const float*)d_in[6];
    const float* bv   = (const float*)d_in[7];
    const float* wo   = (const float*)d_in[8];
    const float* bo   = (const float*)d_in[9];
    const float* w1   = (const float*)d_in[10];
    const float* b1   = (const float*)d_in[11];
    const float* w2   = (const float*)d_in[12];
    const float* b2   = (const float*)d_in[13];
    const float* ln1w = (const float*)d_in[14];
    const float* ln1b = (const float*)d_in[15];
    const float* ln2w = (const float*)d_in[16];
    const float* ln2b = (const float*)d_in[17];
    const float* opsc = (const float*)d_in[18];
    float* out = (float*)d_out;

    float *xq, *q, *k, *v, *ctx, *o, *h, *f, *f2;
    unsigned char *fu;
    signed char *w24;
    float *cs2;
    unsigned int* amax;
    cudaGetSymbolAddress((void**)&xq,  g_xq);
    cudaGetSymbolAddress((void**)&q,   g_q);
    cudaGetSymbolAddress((void**)&k,   g_k);
    cudaGetSymbolAddress((void**)&v,   g_v);
    cudaGetSymbolAddress((void**)&ctx, g_ctx);
    cudaGetSymbolAddress((void**)&o,   g_o);
    cudaGetSymbolAddress((void**)&h,   g_h);
    cudaGetSymbolAddress((void**)&f,   g_f);
    cudaGetSymbolAddress((void**)&f2,  g_f2);
    cudaGetSymbolAddress((void**)&fu,  g_fu);
    cudaGetSymbolAddress((void**)&w24, g_w24);
    cudaGetSymbolAddress((void**)&cs2, g_cs2);
    cudaGetSymbolAddress((void**)&amax, g_amax);

    static const int ATT_SMEM = (64 * QS_LD + 64 * KS_LD + 64 * KS_LD + 128 * PS_LD) * 4;
    cudaFuncSetAttribute(attn_fused, cudaFuncAttributeMaxDynamicSharedMemorySize, ATT_SMEM);
    cudaFuncSetAttribute(gemm_imma, cudaFuncAttributeMaxDynamicSharedMemorySize, G8_TOTAL);

    init_amax_kernel<<<1, 32>>>();
    absmax_kernel<<<1024, 256>>>(x, NX / 4, amax + 0);
    absmax_kernel<<<512, 256>>>(w2, 1048576, amax + 7);

    // FFN2 weight integer split + zero-point row sums
    split_w8_kernel<<<4096, 256>>>(w2, w24, 4194304, amax + 7);
    rowsum_kernel<<<1024, 256>>>(w24, 1024, 4096, amax + 7, cs2);

    // input quantization (R5 path, fp32 qdq values)
    qdq_x_kernel<<<2048, 256>>>(x, xq, amax + 0, NX / 4);

    // QKV projections on the R5 f32x2 GEMM (reference wiring: k<-wv, v<-wk)
    dim3 g64(8, 64);
    gemm_tn<<<g64, 256>>>(xq, wq, q, DD, DD, DD, DD, bq, opsc, 0, 0, nullptr);
    gemm_tn<<<g64, 256>>>(xq, wv, k, DD, DD, DD, DD, bv, opsc, 1, 0, nullptr);
    gemm_tn<<<g64, 256>>>(xq, wk, v, DD, DD, DD, DD, bk, opsc, 2, 0, nullptr);

    // fused attention
    attn_fused<<<dim3(SS / AT_TQ, BB * HH), 256, ATT_SMEM>>>(q, k, v, ctx);

    // ctx requant (dynamic scale) into q buffer; O projection (R5 GEMM)
    absmax_kernel<<<1024, 256>>>(ctx, NX / 4, amax + 1);
    qdq_x_kernel<<<2048, 256>>>(ctx, q, amax + 1, NX / 4);
    gemm_tn<<<g64, 256>>>(q, wo, o, DD, DD, DD, DD, bo, opsc, 3, 0, nullptr);

    // residual + LN1 (bitwise R5)
    add_ln<<<BB * SS, 256>>>(xq, o, ln1w, ln1b, opsc, 8, 6, h);

    // FFN1 on R5 GEMM (bitwise fp32 f) + u8 codes for FFN2's IMMA input
    gemm_tn<<<dim3(32, 64), 256>>>(h, w1, f, DD, DD, FF, DD, b1, opsc, 4, 1, fu);

    // FFN2 on IMMA (R12 config: measured marginal ~1.1e-4)
    gemm_imma<<<dim3(8, 64), 256, G8_TOTAL>>>(fu, w24, 1024, 4096, b2, cs2,
                                              amax + 7, opsc, 4, 5, 0, f2);

    // residual + LN2 -> output
    add_ln<<<BB * SS, 256>>>(h, f2, ln2w, ln2b, opsc, 9, 7, out);
}

// round 16
// speedup vs baseline: 1.2631x; 1.0464x over previous
#include <cuda_runtime.h>
#include <cuda_bf16.h>
#include <math.h>
#include <stdint.h>
#include <stddef.h>

// Problem dims (fixed)
#define BB 4
#define SS 2048
#define DD 1024
#define HH 16
#define HD 64
#define FF 4096

static const size_t NX = (size_t)BB * SS * DD;        // 8388608

// ---------------------------------------------------------------------------
// Scratch (device globals; allocation APIs are forbidden)
__device__ float g_xq [8388608];
__device__ float g_q  [8388608];
__device__ float g_k  [8388608];
__device__ float g_v  [8388608];
__device__ float g_ctx[8388608];
__device__ float g_o  [8388608];
__device__ float g_h  [8388608];
__device__ float g_f  [33554432];
__device__ float g_f2 [8388608];
__device__ unsigned char g_fu  [33554432];  // u8 codes of f   (FFN2 IMMA in)
__device__ unsigned char g_ctxu[8388608];   // u8 codes of ctx (O   IMMA in)
__device__ signed char g_w24[4 * 4194304];
__device__ signed char g_wo4[4 * 1048576];
__device__ float g_cs2[1024];
__device__ float g_cso[1024];
// amax slots: 0=x, 1=ctx, 5=wo, 7=w2
__device__ unsigned int g_amax[8];

// ---------------------------------------------------------------------------
// Packed f32x2 helpers
typedef unsigned long long u64t;
__device__ __forceinline__ u64t pack2(float x, float y) {
    u64t r; asm("mov.b64 %0, {%1, %2};" : "=l"(r) : "f"(x), "f"(y)); return r;
}
__device__ __forceinline__ u64t bcast2(float x) {
    u64t r; asm("mov.b64 %0, {%1, %1};" : "=l"(r) : "f"(x)); return r;
}
__device__ __forceinline__ void fma2(u64t& a, u64t b, u64t c) {
    asm("fma.rn.f32x2 %0, %1, %2, %0;" : "+l"(a) : "l"(b), "l"(c));
}
__device__ __forceinline__ void mul2(u64t& a, u64t s) {
    asm("mul.rn.f32x2 %0, %0, %1;" : "+l"(a) : "l"(s));
}
__device__ __forceinline__ void unpack2(u64t v, float& x, float& y) {
    asm("mov.b64 {%0, %1}, %2;" : "=f"(x), "=f"(y) : "l"(v));
}

// ---------------------------------------------------------------------------
// compute_100-safe tensor-core / async-copy primitives (IMMA path)
__device__ __forceinline__ uint32_t smem_u32(const void* p) {
    uint32_t a;
    asm("{ .reg .u64 t; cvta.to.shared.u64 t, %1; cvt.u32.u64 %0, t; }"
        : "=r"(a) : "l"(p));
    return a;
}
__device__ __forceinline__ void cp_async16(uint32_t saddr, const void* gaddr) {
    asm volatile("cp.async.ca.shared.global [%0], [%1], 16;"
                 :: "r"(saddr), "l"(gaddr) : "memory");
}
#define CP_COMMIT() asm volatile("cp.async.commit_group;" ::: "memory")
#define CP_WAIT1()  asm volatile("cp.async.wait_group 1;" ::: "memory")
#define CP_WAIT0()  asm volatile("cp.async.wait_group 0;" ::: "memory")

__device__ __forceinline__ void ldsm4(uint32_t* r, uint32_t a) {
    asm volatile("ldmatrix.sync.aligned.m8n8.x4.shared.b16 {%0,%1,%2,%3}, [%4];"
                 : "=r"(r[0]), "=r"(r[1]), "=r"(r[2]), "=r"(r[3]) : "r"(a));
}
// Integer MMA: u8 A, s8 B, s32 accumulate (chained). Bit-exact.
__device__ __forceinline__ void imma16832(int* c, const uint32_t* a,
                                          uint32_t b0, uint32_t b1) {
    asm volatile("mma.sync.aligned.m16n8k32.row.col.s32.u8.s8.s32 "
                 "{%0,%1,%2,%3}, {%4,%5,%6,%7}, {%8,%9}, {%0,%1,%2,%3};"
                 : "+r"(c[0]), "+r"(c[1]), "+r"(c[2]), "+r"(c[3])
                 : "r"(a[0]), "r"(a[1]), "r"(a[2]), "r"(a[3]), "r"(b0), "r"(b1));
}

// ---------------------------------------------------------------------------
// qdq matching the JAX fp32 reference (IEEE div, round-half-even)
__device__ __forceinline__ float qdqf(float x, float s) {
    float r = rintf(__fdiv_rn(x, s));
    r = fminf(fmaxf(r + 64.0f, 0.0f), 255.0f);
    return (r - 64.0f) * s;
}

// ---------------------------------------------------------------------------
__global__ void __launch_bounds__(32)
init_amax_kernel() {
    if (threadIdx.x < 8) g_amax[threadIdx.x] = 0u;
}

__global__ void __launch_bounds__(256)
absmax_kernel(const float* __restrict__ X, size_t n4, unsigned int* __restrict__ out) {
    __shared__ float red[8];
    int tid = threadIdx.x;
    size_t i = (size_t)blockIdx.x * blockDim.x + tid;
    size_t stride = (size_t)gridDim.x * blockDim.x;
    const float4* X4 = (const float4*)X;
    float m = 0.0f;
    for (; i < n4; i += stride) {
        float4 v = X4[i];
        m = fmaxf(m, fmaxf(fmaxf(fabsf(v.x), fabsf(v.y)),
                           fmaxf(fabsf(v.z), fabsf(v.w))));
    }
#pragma unroll
    for (int o = 16; o; o >>= 1) m = fmaxf(m, __shfl_xor_sync(0xffffffffu, m, o));
    if ((tid & 31) == 0) red[tid >> 5] = m;
    __syncthreads();
    if (tid == 0) {
        float mm = red[0];
#pragma unroll
        for (int w = 1; w < 8; w++) mm = fmaxf(mm, red[w]);
        atomicMax(out, __float_as_uint(mm));
    }
}

// R5 qdq (fp32 out only) — bitwise identical to the passing kernel
__global__ void __launch_bounds__(256)
qdq_x_kernel(const float* __restrict__ X, float* __restrict__ Xq,
             const unsigned int* __restrict__ amax, size_t n4) {
    float s = __fdiv_rn(__uint_as_float(*amax), 127.0f) + 1e-12f;
    int tid = threadIdx.x;
    size_t i = (size_t)blockIdx.x * blockDim.x + tid;
    size_t stride = (size_t)gridDim.x * blockDim.x;
    const float4* X4 = (const float4*)X;
    float4* O4 = (float4*)Xq;
    for (; i < n4; i += stride) {
        float4 v = X4[i];
        v.x = qdqf(v.x, s); v.y = qdqf(v.y, s);
        v.z = qdqf(v.z, s); v.w = qdqf(v.w, s);
        O4[i] = v;
    }
}

// qdq codes only: u8 q in [0,255] (same rounding sequence as qdqf)
__global__ void __launch_bounds__(256)
qdq_codes_kernel(const float* __restrict__ X, unsigned char* __restrict__ Xu,
                 const unsigned int* __restrict__ amax, size_t n4) {
    float s = __fdiv_rn(__uint_as_float(*amax), 127.0f) + 1e-12f;
    int tid = threadIdx.x;
    size_t i = (size_t)blockIdx.x * blockDim.x + tid;
    size_t stride = (size_t)gridDim.x * blockDim.x;
    const float4* X4 = (const float4*)X;
    for (; i < n4; i += stride) {
        float4 v = X4[i];
        float q0 = fminf(fmaxf(rintf(__fdiv_rn(v.x, s)) + 64.0f, 0.0f), 255.0f);
        float q1 = fminf(fmaxf(rintf(__fdiv_rn(v.y, s)) + 64.0f, 0.0f), 255.0f);
        float q2 = fminf(fmaxf(rintf(__fdiv_rn(v.z, s)) + 64.0f, 0.0f), 255.0f);
        float q3 = fminf(fmaxf(rintf(__fdiv_rn(v.w, s)) + 64.0f, 0.0f), 255.0f);
        uchar4 u;
        u.x = (unsigned char)q0; u.y = (unsigned char)q1;
        u.z = (unsigned char)q2; u.w = (unsigned char)q3;
        *(uchar4*)(Xu + i * 4) = u;
    }
}

// 4-level 7-bit integer split: W = S1 w1 + S2 w2 + S3 w3 + S4 w4 + rho,
// Si = 2^(ev-6-7(i-1)), wi integer in [-64,64] (s8-safe), |rho| <= 2^(ev-28).
__global__ void __launch_bounds__(256)
split_w8_kernel(const float* __restrict__ W, signed char* __restrict__ S, int n,
                const unsigned int* __restrict__ wmaxp) {
    float wmx = __uint_as_float(*wmaxp);
    int ev;
    frexpf(wmx, &ev);
    float S1 = exp2f((float)(ev - 6)),  I1 = exp2f((float)(6 - ev));
    float S2 = exp2f((float)(ev - 13)), I2 = exp2f((float)(13 - ev));
    float S3 = exp2f((float)(ev - 20)), I3 = exp2f((float)(20 - ev));
    float I4 = exp2f((float)(27 - ev));
    int i = blockIdx.x * blockDim.x + threadIdx.x;
    int stride = gridDim.x * blockDim.x;
    for (; i < n; i += stride) {
        float w = W[i];
        float w1 = rintf(w * I1);  float r1 = fmaf(-w1, S1, w);
        float w2 = rintf(r1 * I2); float r2 = fmaf(-w2, S2, r1);
        float w3 = rintf(r2 * I3); float r3 = fmaf(-w3, S3, r2);
        float w4 = rintf(r3 * I4);
        S[i]         = (signed char)__float2int_rn(w1);
        S[n + i]     = (signed char)__float2int_rn(w2);
        S[2 * n + i] = (signed char)__float2int_rn(w3);
        S[3 * n + i] = (signed char)__float2int_rn(w4);
    }
}

// csum[j] = sum_sp S_sp * (integer rowsum of w_sp[j,:])  (zero-point term)
__global__ void __launch_bounds__(256)
rowsum_kernel(const signed char* __restrict__ S, int N, int K,
              const unsigned int* __restrict__ wmaxp, float* __restrict__ csum) {
    __shared__ int red[4][8];
    int j = blockIdx.x, tid = threadIdx.x;
    const size_t sps = (size_t)N * K;
    const signed char* r0 = S + (size_t)j * K;
    int acc[4] = {0, 0, 0, 0};
    for (int k = tid * 4; k < K; k += 1024) {
#pragma unroll
        for (int sp = 0; sp < 4; sp++)
            acc[sp] = __dp4a(*(const int*)(r0 + sp * sps + k), 0x01010101, acc[sp]);
    }
#pragma unroll
    for (int sp = 0; sp < 4; sp++) {
#pragma unroll
        for (int o = 16; o; o >>= 1)
            acc[sp] += __shfl_xor_sync(0xffffffffu, acc[sp], o);
        if ((tid & 31) == 0) red[sp][tid >> 5] = acc[sp];
    }
    __syncthreads();
    if (tid == 0) {
        float wmx = __uint_as_float(*wmaxp);
        int ev;
        frexpf(wmx, &ev);
        float t = 0.0f;
#pragma unroll
        for (int sp = 0; sp < 4; sp++) {
            int s = 0;
#pragma unroll
            for (int w = 0; w < 8; w++) s += red[sp][w];
            t = fmaf(exp2f((float)(ev - 6 - 7 * sp)), (float)s, t);
        }
        csum[j] = t;
    }
}

// ---------------------------------------------------------------------------
// R5 TN SGEMM (f32x2, double-buffered) — fp32 path bitwise identical to the
// passing kernel. Optional u8-code output. Used for QKV, FFN1.
__global__ void __launch_bounds__(256, 2)
gemm_tn(const float* __restrict__ A, const float* __restrict__ Bw,
        float* __restrict__ C, int lda, int ldb, int ldc, int K,
        const float* __restrict__ bias,
        const float* __restrict__ opsc, int sidx, int relu,
        unsigned char* __restrict__ Cu) {
    __shared__ float As[2][16][128];
    __shared__ float Bs[2][16][128];
    const int tid = threadIdx.x;
    const int tx = tid & 15, ty = tid >> 4;
    const size_t bm = (size_t)blockIdx.y * 128;
    const size_t bn = (size_t)blockIdx.x * 128;

    const int r0 = tid >> 2;
    const int r1 = (tid + 256) >> 2;
    const int kq = (tid & 3) << 2;

    const float* Ap0 = A + (bm + r0) * (size_t)lda + kq;
    const float* Ap1 = A + (bm + r1) * (size_t)lda + kq;
    const float* Bp0 = Bw + (bn + r0) * (size_t)ldb + kq;
    const float* Bp1 = Bw + (bn + r1) * (size_t)ldb + kq;

    u64t acc2[8][4];
#pragma unroll
    for (int i = 0; i < 8; i++)
#pragma unroll
        for (int j = 0; j < 4; j++) acc2[i][j] = 0ull;

    float4 ra0 = *(const float4*)(Ap0);
    float4 ra1 = *(const float4*)(Ap1);
    float4 rb0 = *(const float4*)(Bp0);
    float4 rb1 = *(const float4*)(Bp1);

    const int NC = K >> 4;
    for (int c = 0; c < NC; c++) {
        const int buf = c & 1;
        As[buf][kq + 0][r0] = ra0.x; As[buf][kq + 1][r0] = ra0.y;
        As[buf][kq + 2][r0] = ra0.z; As[buf][kq + 3][r0] = ra0.w;
        As[buf][kq + 0][r1] = ra1.x; As[buf][kq + 1][r1] = ra1.y;
        As[buf][kq + 2][r1] = ra1.z; As[buf][kq + 3][r1] = ra1.w;
        Bs[buf][kq + 0][r0] = rb0.x; Bs[buf][kq + 1][r0] = rb0.y;
        Bs[buf][kq + 2][r0] = rb0.z; Bs[buf][kq + 3][r0] = rb0.w;
        Bs[buf][kq + 0][r1] = rb1.x; Bs[buf][kq + 1][r1] = rb1.y;
        Bs[buf][kq + 2][r1] = rb1.z; Bs[buf][kq + 3][r1] = rb1.w;
        __syncthreads();

        if (c + 1 < NC) {
            const int ko = (c + 1) << 4;
            ra0 = *(const float4*)(Ap0 + ko);
            ra1 = *(const float4*)(Ap1 + ko);
            rb0 = *(const float4*)(Bp0 + ko);
            rb1 = *(const float4*)(Bp1 + ko);
        }

#pragma unroll
        for (int kk = 0; kk < 16; kk++) {
            float a0[4], a1[4], b0[4], b1[4];
            *(float4*)a0 = *(const float4*)&As[buf][kk][ty * 4];
            *(float4*)a1 = *(const float4*)&As[buf][kk][64 + ty * 4];
            *(float4*)b0 = *(const float4*)&Bs[buf][kk][tx * 4];
            *(float4*)b1 = *(const float4*)&Bs[buf][kk][64 + tx * 4];
            u64t B2[4];
            B2[0] = pack2(b0[0], b0[1]); B2[1] = pack2(b0[2], b0[3]);
            B2[2] = pack2(b1[0], b1[1]); B2[3] = pack2(b1[2], b1[3]);
#pragma unroll
            for (int i = 0; i < 8; i++) {
                u64t A2 = bcast2((i < 4) ? a0[i] : a1[i - 4]);
                fma2(acc2[i][0], A2, B2[0]);
                fma2(acc2[i][1], A2, B2[1]);
                fma2(acc2[i][2], A2, B2[2]);
                fma2(acc2[i][3], A2, B2[3]);
            }
        }
    }

    float s = (sidx >= 0) ? opsc[sidx] * 0.05f : 0.0f;
#pragma unroll
    for (int i = 0; i < 8; i++) {
        int r = (i < 4) ? (ty * 4 + i) : (64 + ty * 4 + i - 4);
#pragma unroll
        for (int half = 0; half < 2; half++) {
            int c0 = half * 64 + tx * 4;
            float4 v;
            unpack2(acc2[i][half * 2 + 0], v.x, v.y);
            unpack2(acc2[i][half * 2 + 1], v.z, v.w);
            if (bias) {
                float4 b4 = *(const float4*)(bias + bn + c0);
                v.x += b4.x; v.y += b4.y; v.z += b4.z; v.w += b4.w;
            }
            if (relu) {
                v.x = fmaxf(v.x, 0.0f); v.y = fmaxf(v.y, 0.0f);
                v.z = fmaxf(v.z, 0.0f); v.w = fmaxf(v.w, 0.0f);
            }
            size_t g = (bm + r) * (size_t)ldc + bn + c0;
            if (sidx >= 0) {
                float q0 = fminf(fmaxf(rintf(__fdiv_rn(v.x, s)) + 64.0f, 0.0f), 255.0f);
                float q1 = fminf(fmaxf(rintf(__fdiv_rn(v.y, s)) + 64.0f, 0.0f), 255.0f);
                float q2 = fminf(fmaxf(rintf(__fdiv_rn(v.z, s)) + 64.0f, 0.0f), 255.0f);
                float q3 = fminf(fmaxf(rintf(__fdiv_rn(v.w, s)) + 64.0f, 0.0f), 255.0f);
                v.x = (q0 - 64.0f) * s; v.y = (q1 - 64.0f) * s;
                v.z = (q2 - 64.0f) * s; v.w = (q3 - 64.0f) * s;
                if (Cu) {
                    uchar4 u;
                    u.x = (unsigned char)q0; u.y = (unsigned char)q1;
                    u.z = (unsigned char)q2; u.w = (unsigned char)q3;
                    *(uchar4*)(Cu + g) = u;
                }
            }
            *(float4*)(C + g) = v;
        }
    }
}

// ---------------------------------------------------------------------------
// Integer tensor-core TN GEMM (u8 x s8 -> s32) — O (K=1024) + FFN2 (K=4096).
// R12/R15-validated config: s32 chained over 16-chunk (1024-k) groups,
// fp32 fold per group, zero-point (64*csum) subtracted in fp32 epilogue.
// s_a either dynamic (amaxp) or static (opsc[a_sidx]*0.05).
#define G8_STRIDE 80
#define G8_TILE   10240
#define G8_BUF    20480
#define G8_TOTAL  40960

__global__ void __launch_bounds__(256)
gemm_imma(const unsigned char* __restrict__ Aq,
          const signed char* __restrict__ Bsplit,
          int N, int K,
          const float* __restrict__ bias,
          const float* __restrict__ csum,
          const unsigned int* __restrict__ amaxp,
          const unsigned int* __restrict__ wmaxp,
          const float* __restrict__ opsc, int a_sidx, int out_sidx,
          int relu,
          float* __restrict__ Cf) {
    extern __shared__ unsigned char dynsm[];
    const uint32_t s0 = smem_u32(dynsm);

    const int tid = threadIdx.x;
    const int wid = tid >> 5;
    const int lane = tid & 31;
    const int wm = wid & 3;
    const int wn = wid >> 2;

    const size_t bm = (size_t)blockIdx.y * 128;
    const size_t bn = (size_t)blockIdx.x * 128;
    const unsigned char* Ag = Aq + bm * (size_t)K;
    const size_t spstride = (size_t)N * K;

    const int kc = K >> 6;
    const int NCT = 4 * kc;

    float wmx = __uint_as_float(*wmaxp);
    int ev;
    frexpf(wmx, &ev);
    float Ss[4];
#pragma unroll
    for (int sp = 0; sp < 4; sp++) Ss[sp] = exp2f((float)(ev - 6 - 7 * sp));

    int acc_i[2][8][4];
    float acc_f[2][8][4];
#pragma unroll
    for (int mt = 0; mt < 2; mt++)
#pragma unroll
        for (int nt = 0; nt < 8; nt++)
#pragma unroll
            for (int r = 0; r < 4; r++) { acc_i[mt][nt][r] = 0; acc_f[mt][nt][r] = 0.0f; }

    auto load_chunk = [&](int c, int bufsel) {
        int sp = c / kc;
        int kk = (c - sp * kc) << 6;
        const signed char* Bg = Bsplit + (size_t)sp * spstride + bn * (size_t)K;
        uint32_t sa = s0 + bufsel * G8_BUF;
        uint32_t sb = sa + G8_TILE;
#pragma unroll
        for (int j = 0; j < 2; j++) {
            int lin = tid + j * 256;
            int row = lin >> 2;
            int cb = (lin & 3) * 16;
            cp_async16(sa + row * G8_STRIDE + cb, Ag + (size_t)row * K + kk + cb);
            cp_async16(sb + row * G8_STRIDE + cb, Bg + (size_t)row * K + kk + cb);
        }
        CP_COMMIT();
    };

    load_chunk(0, 0);
    if (NCT > 1) load_chunk(1, 1);

    for (int c = 0; c < NCT; c++) {
        if (c + 1 < NCT) { CP_WAIT1(); } else { CP_WAIT0(); }
        __syncthreads();

        uint32_t sa = s0 + (c & 1) * G8_BUF;
        uint32_t sb = sa + G8_TILE;
        uint32_t a_base = sa + (wm * 32 + (lane & 15)) * G8_STRIDE + ((lane >> 4) * 16);
        uint32_t b_base = sb + (wn * 64 + (lane & 15)) * G8_STRIDE + ((lane >> 4) * 16);

#pragma unroll
        for (int ks = 0; ks < 2; ks++) {
            uint32_t ra[2][4];
            ldsm4(ra[0], a_base + ks * 32);
            ldsm4(ra[1], a_base + 16 * G8_STRIDE + ks * 32);
#pragma unroll
            for (int ng = 0; ng < 4; ng++) {
                uint32_t rb[4];
                ldsm4(rb, b_base + ng * 16 * G8_STRIDE + ks * 32);
                imma16832(acc_i[0][2 * ng],     ra[0], rb[0], rb[2]);
                imma16832(acc_i[0][2 * ng + 1], ra[0], rb[1], rb[3]);
                imma16832(acc_i[1][2 * ng],     ra[1], rb[0], rb[2]);
                imma16832(acc_i[1][2 * ng + 1], ra[1], rb[1], rb[3]);
            }
        }

        // fold s32 -> fp32 every 16 chunks (1024 k): |acc_i| < 2^24 => exact cvt
        if (((c + 1) & 15) == 0) {
            float Scur = Ss[c / kc];
#pragma unroll
            for (int mt = 0; mt < 2; mt++)
#pragma unroll
                for (int nt = 0; nt < 8; nt++)
#pragma unroll
                    for (int r = 0; r < 4; r++) {
                        acc_f[mt][nt][r] = fmaf(Scur, (float)acc_i[mt][nt][r],
                                                acc_f[mt][nt][r]);
                        acc_i[mt][nt][r] = 0;
                    }
        }

        __syncthreads();
        if (c + 2 < NCT) load_chunk(c + 2, c & 1);
    }

    float s_a = amaxp ? (__fdiv_rn(__uint_as_float(*amaxp), 127.0f) + 1e-12f)
                      : (opsc[a_sidx] * 0.05f);
    float s_out = opsc[out_sidx] * 0.05f;

#pragma unroll
    for (int mt = 0; mt < 2; mt++) {
        size_t m0 = bm + wm * 32 + mt * 16 + (lane >> 2);
#pragma unroll
        for (int nt = 0; nt < 8; nt++) {
            int n0 = (int)bn + wn * 64 + nt * 8 + (lane & 3) * 2;
            float b0v = bias[n0], b1v = bias[n0 + 1];
            float c0v = csum[n0], c1v = csum[n0 + 1];
            float t0 = fmaf(-64.0f, c0v, acc_f[mt][nt][0]);
            float t1 = fmaf(-64.0f, c1v, acc_f[mt][nt][1]);
            float t2 = fmaf(-64.0f, c0v, acc_f[mt][nt][2]);
            float t3 = fmaf(-64.0f, c1v, acc_f[mt][nt][3]);
            float y0 = fmaf(t0, s_a, b0v);
            float y1 = fmaf(t1, s_a, b1v);
            float y2 = fmaf(t2, s_a, b0v);
            float y3 = fmaf(t3, s_a, b1v);
            if (relu) {
                y0 = fmaxf(y0, 0.0f); y1 = fmaxf(y1, 0.0f);
                y2 = fmaxf(y2, 0.0f); y3 = fmaxf(y3, 0.0f);
            }
            float qv0 = fminf(fmaxf(rintf(__fdiv_rn(y0, s_out)) + 64.0f, 0.0f), 255.0f);
            float qv1 = fminf(fmaxf(rintf(__fdiv_rn(y1, s_out)) + 64.0f, 0.0f), 255.0f);
            float qv2 = fminf(fmaxf(rintf(__fdiv_rn(y2, s_out)) + 64.0f, 0.0f), 255.0f);
            float qv3 = fminf(fmaxf(rintf(__fdiv_rn(y3, s_out)) + 64.0f, 0.0f), 255.0f);
            size_t g0 = m0 * (size_t)N + n0;
            size_t g1 = g0 + 8 * (size_t)N;
            float2 o01; o01.x = (qv0 - 64.0f) * s_out; o01.y = (qv1 - 64.0f) * s_out;
            float2 o23; o23.x = (qv2 - 64.0f) * s_out; o23.y = (qv3 - 64.0f) * s_out;
            *(float2*)(Cf + g0) = o01;
            *(float2*)(Cf + g1) = o23;
        }
    }
}

// ---------------------------------------------------------------------------
// Fused flash-style attention — ctx values bitwise identical to R5/R15;
// additionally folds the ctx abs-max reduction into the epilogue
// (order-independent, value-identical to the separate absmax pass).
#define AT_TQ 128
#define AT_TK 64
#define QS_LD 132
#define KS_LD 68
#define PS_LD 68

__global__ void __launch_bounds__(256, 2)
attn_fused(const float* __restrict__ Q, const float* __restrict__ K,
           const float* __restrict__ V, float* __restrict__ Ctx,
           unsigned int* __restrict__ amax1) {
    extern __shared__ float sm[];
    float* Qs = sm;
    float* Ks = Qs + 64 * QS_LD;
    float* Vs = Ks + 64 * KS_LD;
    float* Ps = Vs + 64 * KS_LD;
    __shared__ float amred[8];

    const int tid = threadIdx.x;
    const int tx = tid & 15, ty = tid >> 4;
    const int z = blockIdx.y, b = z >> 4, h = z & 15;
    const size_t bm = (size_t)blockIdx.x * AT_TQ;
    const float* Qg = Q + ((size_t)b * SS) * DD + h * HD;
    const float* Kg = K + ((size_t)b * SS) * DD + h * HD;
    const float* Vg = V + ((size_t)b * SS) * DD + h * HD;

#pragma unroll
    for (int i = 0; i < 8; i++) {
        int idx = tid + i * 256;
        int r = idx >> 4;
        int q = (idx & 15) << 2;
        float4 v = *(const float4*)(Qg + (bm + r) * (size_t)DD + q);
        Qs[(q + 0) * QS_LD + r] = v.x; Qs[(q + 1) * QS_LD + r] = v.y;
        Qs[(q + 2) * QS_LD + r] = v.z; Qs[(q + 3) * QS_LD + r] = v.w;
    }

    float m_reg[8], l_reg[8];
    u64t acc2[8][2];
#pragma unroll
    for (int i = 0; i < 8; i++) {
        m_reg[i] = -1e30f; l_reg[i] = 0.0f;
        acc2[i][0] = 0ull; acc2[i][1] = 0ull;
    }

    for (int kt0 = 0; kt0 < SS; kt0 += AT_TK) {
        __syncthreads();
#pragma unroll
        for (int i = 0; i < 4; i++) {
            int idx = tid + i * 256;
            int c = idx >> 4;
            int q = (idx & 15) << 2;
            float4 kv = *(const float4*)(Kg + (size_t)(kt0 + c) * DD + q);
            Ks[(q + 0) * KS_LD + c] = kv.x; Ks[(q + 1) * KS_LD + c] = kv.y;
            Ks[(q + 2) * KS_LD + c] = kv.z; Ks[(q + 3) * KS_LD + c] = kv.w;
            float4 vv = *(const float4*)(Vg + (size_t)(kt0 + c) * DD + q);
            *(float4*)&Vs[c * KS_LD + q] = vv;
        }
        __syncthreads();

        u64t s2[8][2];
#pragma unroll
        for (int i = 0; i < 8; i++) { s2[i][0] = 0ull; s2[i][1] = 0ull; }
#pragma unroll 4
        for (int kk = 0; kk < 64; kk++) {
            float a[8], bb[4];
            *(float4*)&a[0] = *(const float4*)&Qs[kk * QS_LD + ty * 8];
            *(float4*)&a[4] = *(const float4*)&Qs[kk * QS_LD + ty * 8 + 4];
            *(float4*)&bb[0] = *(const float4*)&Ks[kk * KS_LD + tx * 4];
            u64t B2[2];
            B2[0] = pack2(bb[0], bb[1]); B2[1] = pack2(bb[2], bb[3]);
#pragma unroll
            for (int i = 0; i < 8; i++) {
                u64t A2 = bcast2(a[i]);
                fma2(s2[i][0], A2, B2[0]);
                fma2(s2[i][1], A2, B2[1]);
            }
        }

#pragma unroll
        for (int i = 0; i < 8; i++) {
            float s[4];
            unpack2(s2[i][0], s[0], s[1]);
            unpack2(s2[i][1], s[2], s[3]);
            float mx = fmaxf(fmaxf(s[0], s[1]), fmaxf(s[2], s[3]));
            mx *= 0.125f;
#pragma unroll
            for (int o = 8; o; o >>= 1)
                mx = fmaxf(mx, __shfl_xor_sync(0xffffffffu, mx, o));
            float mn = fmaxf(m_reg[i], mx);
            float alpha = expf(m_reg[i] - mn);
            float4 p4;
            p4.x = expf(s[0] * 0.125f - mn);
            p4.y = expf(s[1] * 0.125f - mn);
            p4.z = expf(s[2] * 0.125f - mn);
            p4.w = expf(s[3] * 0.125f - mn);
            *(float4*)&Ps[(ty * 8 + i) * PS_LD + tx * 4] = p4;
            float ps = (p4.x + p4.y) + (p4.z + p4.w);
#pragma unroll
            for (int o = 8; o; o >>= 1)
                ps += __shfl_xor_sync(0xffffffffu, ps, o);
            l_reg[i] = l_reg[i] * alpha + ps;
            m_reg[i] = mn;
            u64t al2 = bcast2(alpha);
            mul2(acc2[i][0], al2);
            mul2(acc2[i][1], al2);
        }
        __syncthreads();

#pragma unroll 4
        for (int kt = 0; kt < 64; kt++) {
            float a[8], bb[4];
#pragma unroll
            for (int i = 0; i < 8; i++) a[i] = Ps[(ty * 8 + i) * PS_LD + kt];
            *(float4*)&bb[0] = *(const float4*)&Vs[kt * KS_LD + tx * 4];
            u64t B2[2];
            B2[0] = pack2(bb[0], bb[1]); B2[1] = pack2(bb[2], bb[3]);
#pragma unroll
            for (int i = 0; i < 8; i++) {
                u64t A2 = bcast2(a[i]);
                fma2(acc2[i][0], A2, B2[0]);
                fma2(acc2[i][1], A2, B2[1]);
            }
        }
    }

    float* Cg = Ctx + ((size_t)b * SS) * DD + h * HD;
    float lmax = 0.0f;
#pragma unroll
    for (int i = 0; i < 8; i++) {
        float inv = __fdiv_rn(1.0f, l_reg[i]);
        float4 v;
        unpack2(acc2[i][0], v.x, v.y);
        unpack2(acc2[i][1], v.z, v.w);
        v.x *= inv; v.y *= inv; v.z *= inv; v.w *= inv;
        lmax = fmaxf(lmax, fmaxf(fmaxf(fabsf(v.x), fabsf(v.y)),
                                 fmaxf(fabsf(v.z), fabsf(v.w))));
        *(float4*)(Cg + (bm + ty * 8 + i) * (size_t)DD + tx * 4) = v;
    }
    // fused ctx abs-max (value-identical to the separate absmax pass)
#pragma unroll
    for (int o = 16; o; o >>= 1)
        lmax = fmaxf(lmax, __shfl_xor_sync(0xffffffffu, lmax, o));
    if ((tid & 31) == 0) amred[tid >> 5] = lmax;
    __syncthreads();
    if (tid == 0) {
        float mm = amred[0];
#pragma unroll
        for (int w = 1; w < 8; w++) mm = fmaxf(mm, amred[w]);
        atomicMax(amax1, __float_as_uint(mm));
    }
}

// ---------------------------------------------------------------------------
// t = qdq(X+Y, s[sa]); Out = qdq(layernorm(t)*w+b, s[sl]).  Bitwise R5 path.
__global__ void __launch_bounds__(256)
add_ln(const float* __restrict__ X, const float* __restrict__ Y,
       const float* __restrict__ w, const float* __restrict__ bvec,
       const float* __restrict__ opsc, int sa, int sl,
       float* __restrict__ Out) {
    __shared__ float red[8];
    const int tid = threadIdx.x;
    const size_t base = (size_t)blockIdx.x * 1024;
    const float s_add = opsc[sa] * 0.05f;
    const float s_ln  = opsc[sl] * 0.05f;
    const int c = tid * 4;
    float4 xv = *(const float4*)(X + base + c);
    float4 yv = *(const float4*)(Y + base + c);
    float v0 = qdqf(xv.x + yv.x, s_add);
    float v1 = qdqf(xv.y + yv.y, s_add);
    float v2 = qdqf(xv.z + yv.z, s_add);
    float v3 = qdqf(xv.w + yv.w, s_add);

    float lsum = (v0 + v1) + (v2 + v3);
#pragma unroll
    for (int o = 16; o; o >>= 1) lsum += __shfl_xor_sync(0xffffffffu, lsum, o);
    if ((tid & 31) == 0) red[tid >> 5] = lsum;
    __syncthreads();
    float tot = 0.0f;
#pragma unroll
    for (int ww = 0; ww < 8; ww++) tot += red[ww];
    float mu = tot * (1.0f / 1024.0f);

    float d0 = v0 - mu, d1 = v1 - mu, d2 = v2 - mu, d3 = v3 - mu;
    float lv = d0 * d0 + d1 * d1 + d2 * d2 + d3 * d3;
#pragma unroll
    for (int o = 16; o; o >>= 1) lv += __shfl_xor_sync(0xffffffffu, lv, o);
    __syncthreads();
    if ((tid & 31) == 0) red[tid >> 5] = lv;
    __syncthreads();
    float vtot = 0.0f;
#pragma unroll
    for (int ww = 0; ww < 8; ww++) vtot += red[ww];
    float var = vtot * (1.0f / 1024.0f);
    float rstd = __fdiv_rn(1.0f, __fsqrt_rn(var + 1e-5f));

    float4 w4 = *(const float4*)(w + c);
    float4 b4 = *(const float4*)(bvec + c);
    float4 o4;
    o4.x = qdqf(d0 * rstd * w4.x + b4.x, s_ln);
    o4.y = qdqf(d1 * rstd * w4.y + b4.y, s_ln);
    o4.z = qdqf(d2 * rstd * w4.z + b4.z, s_ln);
    o4.w = qdqf(d3 * rstd * w4.w + b4.w, s_ln);
    *(float4*)(Out + base + c) = o4;
}

// ---------------------------------------------------------------------------
extern "C" void kernel_launch(void* const* d_in, const int* in_sizes, int n_in,
                              void* d_out, int out_size) {
    const float* x    = (const float*)d_in[0];
    const float* wq   = (const float*)d_in[2];
    const float* bq   = (const float*)d_in[3];
    const float* wk   = (const float*)d_in[4];
    const float* bk   = (const float*)d_in[5];
    const float* wv   = (const float*)d_in[6];
    const float* bv   = (const float*)d_in[7];
    const float* wo   = (const float*)d_in[8];
    const float* bo   = (const float*)d_in[9];
    const float* w1   = (const float*)d_in[10];
    const float* b1   = (const float*)d_in[11];
    const float* w2   = (const float*)d_in[12];
    const float* b2   = (const float*)d_in[13];
    const float* ln1w = (const float*)d_in[14];
    const float* ln1b = (const float*)d_in[15];
    const float* ln2w = (const float*)d_in[16];
    const float* ln2b = (const float*)d_in[17];
    const float* opsc = (const float*)d_in[18];
    float* out = (float*)d_out;

    float *xq, *q, *k, *v, *ctx, *o, *h, *f, *f2;
    unsigned char *fu, *ctxu;
    signed char *w24, *wo4;
    float *cs2, *cso;
    unsigned int* amax;
    cudaGetSymbolAddress((void**)&xq,  g_xq);
    cudaGetSymbolAddress((void**)&q,   g_q);
    cudaGetSymbolAddress((void**)&k,   g_k);
    cudaGetSymbolAddress((void**)&v,   g_v);
    cudaGetSymbolAddress((void**)&ctx, g_ctx);
    cudaGetSymbolAddress((void**)&o,   g_o);
    cudaGetSymbolAddress((void**)&h,   g_h);
    cudaGetSymbolAddress((void**)&f,   g_f);
    cudaGetSymbolAddress((void**)&f2,  g_f2);
    cudaGetSymbolAddress((void**)&fu,  g_fu);
    cudaGetSymbolAddress((void**)&ctxu, g_ctxu);
    cudaGetSymbolAddress((void**)&w24, g_w24);
    cudaGetSymbolAddress((void**)&wo4, g_wo4);
    cudaGetSymbolAddress((void**)&cs2, g_cs2);
    cudaGetSymbolAddress((void**)&cso, g_cso);
    cudaGetSymbolAddress((void**)&amax, g_amax);

    static const int ATT_SMEM = (64 * QS_LD + 64 * KS_LD + 64 * KS_LD + 128 * PS_LD) * 4;
    cudaFuncSetAttribute(attn_fused, cudaFuncAttributeMaxDynamicSharedMemorySize, ATT_SMEM);
    cudaFuncSetAttribute(gemm_imma, cudaFuncAttributeMaxDynamicSharedMemorySize, G8_TOTAL);

    init_amax_kernel<<<1, 32>>>();
    absmax_kernel<<<1024, 256>>>(x, NX / 4, amax + 0);
    absmax_kernel<<<256, 256>>>(wo, 262144, amax + 5);
    absmax_kernel<<<512, 256>>>(w2, 1048576, amax + 7);

    // O + FFN2 weight integer splits + zero-point row sums
    split_w8_kernel<<<2048, 256>>>(wo, wo4, 1048576, amax + 5);
    split_w8_kernel<<<4096, 256>>>(w2, w24, 4194304, amax + 7);
    rowsum_kernel<<<1024, 256>>>(wo4, 1024, 1024, amax + 5, cso);
    rowsum_kernel<<<1024, 256>>>(w24, 1024, 4096, amax + 7, cs2);

    // input quantization (R5 path, fp32 qdq values)
    qdq_x_kernel<<<2048, 256>>>(x, xq, amax + 0, NX / 4);

    // QKV projections on the R5 f32x2 GEMM (reference wiring: k<-wv, v<-wk)
    dim3 g64(8, 64);
    gemm_tn<<<g64, 256>>>(xq, wq, q, DD, DD, DD, DD, bq, opsc, 0, 0, nullptr);
    gemm_tn<<<g64, 256>>>(xq, wv, k, DD, DD, DD, DD, bv, opsc, 1, 0, nullptr);
    gemm_tn<<<g64, 256>>>(xq, wk, v, DD, DD, DD, DD, bk, opsc, 2, 0, nullptr);

    // fused attention (+ fused ctx abs-max into amax[1])
    attn_fused<<<dim3(SS / AT_TQ, BB * HH), 256, ATT_SMEM>>>(q, k, v, ctx, amax + 1);

    // ctx codes (dynamic scale); O projection on IMMA (delta under test)
    qdq_codes_kernel<<<2048, 256>>>(ctx, ctxu, amax + 1, NX / 4);
    gemm_imma<<<dim3(8, 64), 256, G8_TOTAL>>>(ctxu, wo4, 1024, 1024, bo, cso,
                                              amax + 1, amax + 5, opsc, 0, 3, 0, o);

    // residual + LN1 (bitwise R5)
    add_ln<<<BB * SS, 256>>>(xq, o, ln1w, ln1b, opsc, 8, 6, h);

    // FFN1 on R5 GEMM (bitwise fp32 f) + u8 codes for FFN2's IMMA input
    gemm_tn<<<dim3(32, 64), 256>>>(h, w1, f, DD, DD, FF, DD, b1, opsc, 4, 1, fu);

    // FFN2 on IMMA (banked R15 config)
    gemm_imma<<<dim3(8, 64), 256, G8_TOTAL>>>(fu, w24, 1024, 4096, b2, cs2,
                                              nullptr, amax + 7, opsc, 4, 5, 0, f2);

    // residual + LN2 -> output
    add_ln<<<BB * SS, 256>>>(h, f2, ln2w, ln2b, opsc, 9, 7, out);
}

// round 17
// speedup vs baseline: 1.3013x; 1.0303x over previous
#include <cuda_runtime.h>
#include <cuda_bf16.h>
#include <math.h>
#include <stdint.h>
#include <stddef.h>

// Problem dims (fixed)
#define BB 4
#define SS 2048
#define DD 1024
#define HH 16
#define HD 64
#define FF 4096

static const size_t NX = (size_t)BB * SS * DD;        // 8388608

// ---------------------------------------------------------------------------
// Scratch (device globals; allocation APIs are forbidden)
__device__ float g_xq [8388608];
__device__ float g_q  [8388608];
__device__ float g_k  [8388608];
__device__ float g_v  [8388608];
__device__ float g_ctx[8388608];
__device__ float g_o  [8388608];
__device__ float g_h  [8388608];
__device__ float g_f2 [8388608];
__device__ unsigned char g_fu  [33554432];  // u8 codes of f   (FFN2 IMMA in)
__device__ unsigned char g_ctxu[8388608];   // u8 codes of ctx (O   IMMA in)
__device__ signed char g_w24[4 * 4194304];
__device__ signed char g_wo4[4 * 1048576];
__device__ float g_cs2[1024];
__device__ float g_cso[1024];
// amax slots: 0=x, 1=ctx, 5=wo, 7=w2
__device__ unsigned int g_amax[8];

// ---------------------------------------------------------------------------
// Packed f32x2 helpers
typedef unsigned long long u64t;
__device__ __forceinline__ u64t pack2(float x, float y) {
    u64t r; asm("mov.b64 %0, {%1, %2};" : "=l"(r) : "f"(x), "f"(y)); return r;
}
__device__ __forceinline__ u64t bcast2(float x) {
    u64t r; asm("mov.b64 %0, {%1, %1};" : "=l"(r) : "f"(x)); return r;
}
__device__ __forceinline__ void fma2(u64t& a, u64t b, u64t c) {
    asm("fma.rn.f32x2 %0, %1, %2, %0;" : "+l"(a) : "l"(b), "l"(c));
}
__device__ __forceinline__ void mul2(u64t& a, u64t s) {
    asm("mul.rn.f32x2 %0, %0, %1;" : "+l"(a) : "l"(s));
}
__device__ __forceinline__ void unpack2(u64t v, float& x, float& y) {
    asm("mov.b64 {%0, %1}, %2;" : "=f"(x), "=f"(y) : "l"(v));
}

// ---------------------------------------------------------------------------
// compute_100-safe tensor-core / async-copy primitives
__device__ __forceinline__ uint32_t smem_u32(const void* p) {
    uint32_t a;
    asm("{ .reg .u64 t; cvta.to.shared.u64 t, %1; cvt.u32.u64 %0, t; }"
        : "=r"(a) : "l"(p));
    return a;
}
__device__ __forceinline__ void cp_async16(uint32_t saddr, const void* gaddr) {
    asm volatile("cp.async.ca.shared.global [%0], [%1], 16;"
                 :: "r"(saddr), "l"(gaddr) : "memory");
}
#define CP_COMMIT() asm volatile("cp.async.commit_group;" ::: "memory")
#define CP_WAIT1()  asm volatile("cp.async.wait_group 1;" ::: "memory")
#define CP_WAIT0()  asm volatile("cp.async.wait_group 0;" ::: "memory")

__device__ __forceinline__ void ldsm4(uint32_t* r, uint32_t a) {
    asm volatile("ldmatrix.sync.aligned.m8n8.x4.shared.b16 {%0,%1,%2,%3}, [%4];"
                 : "=r"(r[0]), "=r"(r[1]), "=r"(r[2]), "=r"(r[3]) : "r"(a));
}
// Integer MMA: u8 A, s8 B, s32 accumulate (chained). Bit-exact.
__device__ __forceinline__ void imma16832(int* c, const uint32_t* a,
                                          uint32_t b0, uint32_t b1) {
    asm volatile("mma.sync.aligned.m16n8k32.row.col.s32.u8.s8.s32 "
                 "{%0,%1,%2,%3}, {%4,%5,%6,%7}, {%8,%9}, {%0,%1,%2,%3};"
                 : "+r"(c[0]), "+r"(c[1]), "+r"(c[2]), "+r"(c[3])
                 : "r"(a[0]), "r"(a[1]), "r"(a[2]), "r"(a[3]), "r"(b0), "r"(b1));
}

// ---------------------------------------------------------------------------
// qdq matching the JAX fp32 reference (IEEE div, round-half-even)
__device__ __forceinline__ float qdqf(float x, float s) {
    float r = rintf(__fdiv_rn(x, s));
    r = fminf(fmaxf(r + 64.0f, 0.0f), 255.0f);
    return (r - 64.0f) * s;
}

// ---------------------------------------------------------------------------
__global__ void __launch_bounds__(32)
init_amax_kernel() {
    if (threadIdx.x < 8) g_amax[threadIdx.x] = 0u;
}

__global__ void __launch_bounds__(256)
absmax_kernel(const float* __restrict__ X, size_t n4, unsigned int* __restrict__ out) {
    __shared__ float red[8];
    int tid = threadIdx.x;
    size_t i = (size_t)blockIdx.x * blockDim.x + tid;
    size_t stride = (size_t)gridDim.x * blockDim.x;
    const float4* X4 = (const float4*)X;
    float m = 0.0f;
    for (; i < n4; i += stride) {
        float4 v = X4[i];
        m = fmaxf(m, fmaxf(fmaxf(fabsf(v.x), fabsf(v.y)),
                           fmaxf(fabsf(v.z), fabsf(v.w))));
    }
#pragma unroll
    for (int o = 16; o; o >>= 1) m = fmaxf(m, __shfl_xor_sync(0xffffffffu, m, o));
    if ((tid & 31) == 0) red[tid >> 5] = m;
    __syncthreads();
    if (tid == 0) {
        float mm = red[0];
#pragma unroll
        for (int w = 1; w < 8; w++) mm = fmaxf(mm, red[w]);
        atomicMax(out, __float_as_uint(mm));
    }
}

// R5 qdq (fp32 out only) — bitwise identical to the passing kernel
__global__ void __launch_bounds__(256)
qdq_x_kernel(const float* __restrict__ X, float* __restrict__ Xq,
             const unsigned int* __restrict__ amax, size_t n4) {
    float s = __fdiv_rn(__uint_as_float(*amax), 127.0f) + 1e-12f;
    int tid = threadIdx.x;
    size_t i = (size_t)blockIdx.x * blockDim.x + tid;
    size_t stride = (size_t)gridDim.x * blockDim.x;
    const float4* X4 = (const float4*)X;
    float4* O4 = (float4*)Xq;
    for (; i < n4; i += stride) {
        float4 v = X4[i];
        v.x = qdqf(v.x, s); v.y = qdqf(v.y, s);
        v.z = qdqf(v.z, s); v.w = qdqf(v.w, s);
        O4[i] = v;
    }
}

// qdq codes only: u8 q in [0,255] (same rounding sequence as qdqf)
__global__ void __launch_bounds__(256)
qdq_codes_kernel(const float* __restrict__ X, unsigned char* __restrict__ Xu,
                 const unsigned int* __restrict__ amax, size_t n4) {
    float s = __fdiv_rn(__uint_as_float(*amax), 127.0f) + 1e-12f;
    int tid = threadIdx.x;
    size_t i = (size_t)blockIdx.x * blockDim.x + tid;
    size_t stride = (size_t)gridDim.x * blockDim.x;
    const float4* X4 = (const float4*)X;
    for (; i < n4; i += stride) {
        float4 v = X4[i];
        float q0 = fminf(fmaxf(rintf(__fdiv_rn(v.x, s)) + 64.0f, 0.0f), 255.0f);
        float q1 = fminf(fmaxf(rintf(__fdiv_rn(v.y, s)) + 64.0f, 0.0f), 255.0f);
        float q2 = fminf(fmaxf(rintf(__fdiv_rn(v.z, s)) + 64.0f, 0.0f), 255.0f);
        float q3 = fminf(fmaxf(rintf(__fdiv_rn(v.w, s)) + 64.0f, 0.0f), 255.0f);
        uchar4 u;
        u.x = (unsigned char)q0; u.y = (unsigned char)q1;
        u.z = (unsigned char)q2; u.w = (unsigned char)q3;
        *(uchar4*)(Xu + i * 4) = u;
    }
}

// 4-level 7-bit integer split: W = S1 w1 + S2 w2 + S3 w3 + S4 w4 + rho.
__global__ void __launch_bounds__(256)
split_w8_kernel(const float* __restrict__ W, signed char* __restrict__ S, int n,
                const unsigned int* __restrict__ wmaxp) {
    float wmx = __uint_as_float(*wmaxp);
    int ev;
    frexpf(wmx, &ev);
    float S1 = exp2f((float)(ev - 6)),  I1 = exp2f((float)(6 - ev));
    float S2 = exp2f((float)(ev - 13)), I2 = exp2f((float)(13 - ev));
    float S3 = exp2f((float)(ev - 20)), I3 = exp2f((float)(20 - ev));
    float I4 = exp2f((float)(27 - ev));
    int i = blockIdx.x * blockDim.x + threadIdx.x;
    int stride = gridDim.x * blockDim.x;
    for (; i < n; i += stride) {
        float w = W[i];
        float w1 = rintf(w * I1);  float r1 = fmaf(-w1, S1, w);
        float w2 = rintf(r1 * I2); float r2 = fmaf(-w2, S2, r1);
        float w3 = rintf(r2 * I3); float r3 = fmaf(-w3, S3, r2);
        float w4 = rintf(r3 * I4);
        S[i]         = (signed char)__float2int_rn(w1);
        S[n + i]     = (signed char)__float2int_rn(w2);
        S[2 * n + i] = (signed char)__float2int_rn(w3);
        S[3 * n + i] = (signed char)__float2int_rn(w4);
    }
}

// csum[j] = sum_sp S_sp * (integer rowsum of w_sp[j,:])  (zero-point term)
__global__ void __launch_bounds__(256)
rowsum_kernel(const signed char* __restrict__ S, int N, int K,
              const unsigned int* __restrict__ wmaxp, float* __restrict__ csum) {
    __shared__ int red[4][8];
    int j = blockIdx.x, tid = threadIdx.x;
    const size_t sps = (size_t)N * K;
    const signed char* r0 = S + (size_t)j * K;
    int acc[4] = {0, 0, 0, 0};
    for (int k = tid * 4; k < K; k += 1024) {
#pragma unroll
        for (int sp = 0; sp < 4; sp++)
            acc[sp] = __dp4a(*(const int*)(r0 + sp * sps + k), 0x01010101, acc[sp]);
    }
#pragma unroll
    for (int sp = 0; sp < 4; sp++) {
#pragma unroll
        for (int o = 16; o; o >>= 1)
            acc[sp] += __shfl_xor_sync(0xffffffffu, acc[sp], o);
        if ((tid & 31) == 0) red[sp][tid >> 5] = acc[sp];
    }
    __syncthreads();
    if (tid == 0) {
        float wmx = __uint_as_float(*wmaxp);
        int ev;
        frexpf(wmx, &ev);
        float t = 0.0f;
#pragma unroll
        for (int sp = 0; sp < 4; sp++) {
            int s = 0;
#pragma unroll
            for (int w = 0; w < 8; w++) s += red[sp][w];
            t = fmaf(exp2f((float)(ev - 6 - 7 * sp)), (float)s, t);
        }
        csum[j] = t;
    }
}

// ---------------------------------------------------------------------------
// R5 TN SGEMM (f32x2, double-buffered) — fp32 values bitwise identical to the
// passing kernel. Optional u8-code output; optional fp32 store (C nullable).
__global__ void __launch_bounds__(256, 2)
gemm_tn(const float* __restrict__ A, const float* __restrict__ Bw,
        float* __restrict__ C, int lda, int ldb, int ldc, int K,
        const float* __restrict__ bias,
        const float* __restrict__ opsc, int sidx, int relu,
        unsigned char* __restrict__ Cu) {
    __shared__ float As[2][16][128];
    __shared__ float Bs[2][16][128];
    const int tid = threadIdx.x;
    const int tx = tid & 15, ty = tid >> 4;
    const size_t bm = (size_t)blockIdx.y * 128;
    const size_t bn = (size_t)blockIdx.x * 128;

    const int r0 = tid >> 2;
    const int r1 = (tid + 256) >> 2;
    const int kq = (tid & 3) << 2;

    const float* Ap0 = A + (bm + r0) * (size_t)lda + kq;
    const float* Ap1 = A + (bm + r1) * (size_t)lda + kq;
    const float* Bp0 = Bw + (bn + r0) * (size_t)ldb + kq;
    const float* Bp1 = Bw + (bn + r1) * (size_t)ldb + kq;

    u64t acc2[8][4];
#pragma unroll
    for (int i = 0; i < 8; i++)
#pragma unroll
        for (int j = 0; j < 4; j++) acc2[i][j] = 0ull;

    float4 ra0 = *(const float4*)(Ap0);
    float4 ra1 = *(const float4*)(Ap1);
    float4 rb0 = *(const float4*)(Bp0);
    float4 rb1 = *(const float4*)(Bp1);

    const int NC = K >> 4;
    for (int c = 0; c < NC; c++) {
        const int buf = c & 1;
        As[buf][kq + 0][r0] = ra0.x; As[buf][kq + 1][r0] = ra0.y;
        As[buf][kq + 2][r0] = ra0.z; As[buf][kq + 3][r0] = ra0.w;
        As[buf][kq + 0][r1] = ra1.x; As[buf][kq + 1][r1] = ra1.y;
        As[buf][kq + 2][r1] = ra1.z; As[buf][kq + 3][r1] = ra1.w;
        Bs[buf][kq + 0][r0] = rb0.x; Bs[buf][kq + 1][r0] = rb0.y;
        Bs[buf][kq + 2][r0] = rb0.z; Bs[buf][kq + 3][r0] = rb0.w;
        Bs[buf][kq + 0][r1] = rb1.x; Bs[buf][kq + 1][r1] = rb1.y;
        Bs[buf][kq + 2][r1] = rb1.z; Bs[buf][kq + 3][r1] = rb1.w;
        __syncthreads();

        if (c + 1 < NC) {
            const int ko = (c + 1) << 4;
            ra0 = *(const float4*)(Ap0 + ko);
            ra1 = *(const float4*)(Ap1 + ko);
            rb0 = *(const float4*)(Bp0 + ko);
            rb1 = *(const float4*)(Bp1 + ko);
        }

#pragma unroll
        for (int kk = 0; kk < 16; kk++) {
            float a0[4], a1[4], b0[4], b1[4];
            *(float4*)a0 = *(const float4*)&As[buf][kk][ty * 4];
            *(float4*)a1 = *(const float4*)&As[buf][kk][64 + ty * 4];
            *(float4*)b0 = *(const float4*)&Bs[buf][kk][tx * 4];
            *(float4*)b1 = *(const float4*)&Bs[buf][kk][64 + tx * 4];
            u64t B2[4];
            B2[0] = pack2(b0[0], b0[1]); B2[1] = pack2(b0[2], b0[3]);
            B2[2] = pack2(b1[0], b1[1]); B2[3] = pack2(b1[2], b1[3]);
#pragma unroll
            for (int i = 0; i < 8; i++) {
                u64t A2 = bcast2((i < 4) ? a0[i] : a1[i - 4]);
                fma2(acc2[i][0], A2, B2[0]);
                fma2(acc2[i][1], A2, B2[1]);
                fma2(acc2[i][2], A2, B2[2]);
                fma2(acc2[i][3], A2, B2[3]);
            }
        }
    }

    float s = (sidx >= 0) ? opsc[sidx] * 0.05f : 0.0f;
#pragma unroll
    for (int i = 0; i < 8; i++) {
        int r = (i < 4) ? (ty * 4 + i) : (64 + ty * 4 + i - 4);
#pragma unroll
        for (int half = 0; half < 2; half++) {
            int c0 = half * 64 + tx * 4;
            float4 v;
            unpack2(acc2[i][half * 2 + 0], v.x, v.y);
            unpack2(acc2[i][half * 2 + 1], v.z, v.w);
            if (bias) {
                float4 b4 = *(const float4*)(bias + bn + c0);
                v.x += b4.x; v.y += b4.y; v.z += b4.z; v.w += b4.w;
            }
            if (relu) {
                v.x = fmaxf(v.x, 0.0f); v.y = fmaxf(v.y, 0.0f);
                v.z = fmaxf(v.z, 0.0f); v.w = fmaxf(v.w, 0.0f);
            }
            size_t g = (bm + r) * (size_t)ldc + bn + c0;
            if (sidx >= 0) {
                float q0 = fminf(fmaxf(rintf(__fdiv_rn(v.x, s)) + 64.0f, 0.0f), 255.0f);
                float q1 = fminf(fmaxf(rintf(__fdiv_rn(v.y, s)) + 64.0f, 0.0f), 255.0f);
                float q2 = fminf(fmaxf(rintf(__fdiv_rn(v.z, s)) + 64.0f, 0.0f), 255.0f);
                float q3 = fminf(fmaxf(rintf(__fdiv_rn(v.w, s)) + 64.0f, 0.0f), 255.0f);
                v.x = (q0 - 64.0f) * s; v.y = (q1 - 64.0f) * s;
                v.z = (q2 - 64.0f) * s; v.w = (q3 - 64.0f) * s;
                if (Cu) {
                    uchar4 u;
                    u.x = (unsigned char)q0; u.y = (unsigned char)q1;
                    u.z = (unsigned char)q2; u.w = (unsigned char)q3;
                    *(uchar4*)(Cu + g) = u;
                }
            }
            if (C) *(float4*)(C + g) = v;
        }
    }
}

// ---------------------------------------------------------------------------
// Integer tensor-core TN GEMM (u8 x s8 -> s32) — O (K=1024) + FFN2 (K=4096).
#define G8_STRIDE 80
#define G8_TILE   10240
#define G8_BUF    20480
#define G8_TOTAL  40960

__global__ void __launch_bounds__(256)
gemm_imma(const unsigned char* __restrict__ Aq,
          const signed char* __restrict__ Bsplit,
          int N, int K,
          const float* __restrict__ bias,
          const float* __restrict__ csum,
          const unsigned int* __restrict__ amaxp,
          const unsigned int* __restrict__ wmaxp,
          const float* __restrict__ opsc, int a_sidx, int out_sidx,
          int relu,
          float* __restrict__ Cf) {
    extern __shared__ unsigned char dynsm[];
    const uint32_t s0 = smem_u32(dynsm);

    const int tid = threadIdx.x;
    const int wid = tid >> 5;
    const int lane = tid & 31;
    const int wm = wid & 3;
    const int wn = wid >> 2;

    const size_t bm = (size_t)blockIdx.y * 128;
    const size_t bn = (size_t)blockIdx.x * 128;
    const unsigned char* Ag = Aq + bm * (size_t)K;
    const size_t spstride = (size_t)N * K;

    const int kc = K >> 6;
    const int NCT = 4 * kc;

    float wmx = __uint_as_float(*wmaxp);
    int ev;
    frexpf(wmx, &ev);
    float Ss[4];
#pragma unroll
    for (int sp = 0; sp < 4; sp++) Ss[sp] = exp2f((float)(ev - 6 - 7 * sp));

    int acc_i[2][8][4];
    float acc_f[2][8][4];
#pragma unroll
    for (int mt = 0; mt < 2; mt++)
#pragma unroll
        for (int nt = 0; nt < 8; nt++)
#pragma unroll
            for (int r = 0; r < 4; r++) { acc_i[mt][nt][r] = 0; acc_f[mt][nt][r] = 0.0f; }

    auto load_chunk = [&](int c, int bufsel) {
        int sp = c / kc;
        int kk = (c - sp * kc) << 6;
        const signed char* Bg = Bsplit + (size_t)sp * spstride + bn * (size_t)K;
        uint32_t sa = s0 + bufsel * G8_BUF;
        uint32_t sb = sa + G8_TILE;
#pragma unroll
        for (int j = 0; j < 2; j++) {
            int lin = tid + j * 256;
            int row = lin >> 2;
            int cb = (lin & 3) * 16;
            cp_async16(sa + row * G8_STRIDE + cb, Ag + (size_t)row * K + kk + cb);
            cp_async16(sb + row * G8_STRIDE + cb, Bg + (size_t)row * K + kk + cb);
        }
        CP_COMMIT();
    };

    load_chunk(0, 0);
    if (NCT > 1) load_chunk(1, 1);

    for (int c = 0; c < NCT; c++) {
        if (c + 1 < NCT) { CP_WAIT1(); } else { CP_WAIT0(); }
        __syncthreads();

        uint32_t sa = s0 + (c & 1) * G8_BUF;
        uint32_t sb = sa + G8_TILE;
        uint32_t a_base = sa + (wm * 32 + (lane & 15)) * G8_STRIDE + ((lane >> 4) * 16);
        uint32_t b_base = sb + (wn * 64 + (lane & 15)) * G8_STRIDE + ((lane >> 4) * 16);

#pragma unroll
        for (int ks = 0; ks < 2; ks++) {
            uint32_t ra[2][4];
            ldsm4(ra[0], a_base + ks * 32);
            ldsm4(ra[1], a_base + 16 * G8_STRIDE + ks * 32);
#pragma unroll
            for (int ng = 0; ng < 4; ng++) {
                uint32_t rb[4];
                ldsm4(rb, b_base + ng * 16 * G8_STRIDE + ks * 32);
                imma16832(acc_i[0][2 * ng],     ra[0], rb[0], rb[2]);
                imma16832(acc_i[0][2 * ng + 1], ra[0], rb[1], rb[3]);
                imma16832(acc_i[1][2 * ng],     ra[1], rb[0], rb[2]);
                imma16832(acc_i[1][2 * ng + 1], ra[1], rb[1], rb[3]);
            }
        }

        if (((c + 1) & 15) == 0) {
            float Scur = Ss[c / kc];
#pragma unroll
            for (int mt = 0; mt < 2; mt++)
#pragma unroll
                for (int nt = 0; nt < 8; nt++)
#pragma unroll
                    for (int r = 0; r < 4; r++) {
                        acc_f[mt][nt][r] = fmaf(Scur, (float)acc_i[mt][nt][r],
                                                acc_f[mt][nt][r]);
                        acc_i[mt][nt][r] = 0;
                    }
        }

        __syncthreads();
        if (c + 2 < NCT) load_chunk(c + 2, c & 1);
    }

    float s_a = amaxp ? (__fdiv_rn(__uint_as_float(*amaxp), 127.0f) + 1e-12f)
                      : (opsc[a_sidx] * 0.05f);
    float s_out = opsc[out_sidx] * 0.05f;

#pragma unroll
    for (int mt = 0; mt < 2; mt++) {
        size_t m0 = bm + wm * 32 + mt * 16 + (lane >> 2);
#pragma unroll
        for (int nt = 0; nt < 8; nt++) {
            int n0 = (int)bn + wn * 64 + nt * 8 + (lane & 3) * 2;
            float b0v = bias[n0], b1v = bias[n0 + 1];
            float c0v = csum[n0], c1v = csum[n0 + 1];
            float t0 = fmaf(-64.0f, c0v, acc_f[mt][nt][0]);
            float t1 = fmaf(-64.0f, c1v, acc_f[mt][nt][1]);
            float t2 = fmaf(-64.0f, c0v, acc_f[mt][nt][2]);
            float t3 = fmaf(-64.0f, c1v, acc_f[mt][nt][3]);
            float y0 = fmaf(t0, s_a, b0v);
            float y1 = fmaf(t1, s_a, b1v);
            float y2 = fmaf(t2, s_a, b0v);
            float y3 = fmaf(t3, s_a, b1v);
            if (relu) {
                y0 = fmaxf(y0, 0.0f); y1 = fmaxf(y1, 0.0f);
                y2 = fmaxf(y2, 0.0f); y3 = fmaxf(y3, 0.0f);
            }
            float qv0 = fminf(fmaxf(rintf(__fdiv_rn(y0, s_out)) + 64.0f, 0.0f), 255.0f);
            float qv1 = fminf(fmaxf(rintf(__fdiv_rn(y1, s_out)) + 64.0f, 0.0f), 255.0f);
            float qv2 = fminf(fmaxf(rintf(__fdiv_rn(y2, s_out)) + 64.0f, 0.0f), 255.0f);
            float qv3 = fminf(fmaxf(rintf(__fdiv_rn(y3, s_out)) + 64.0f, 0.0f), 255.0f);
            size_t g0 = m0 * (size_t)N + n0;
            size_t g1 = g0 + 8 * (size_t)N;
            float2 o01; o01.x = (qv0 - 64.0f) * s_out; o01.y = (qv1 - 64.0f) * s_out;
            float2 o23; o23.x = (qv2 - 64.0f) * s_out; o23.y = (qv3 - 64.0f) * s_out;
            *(float2*)(Cf + g0) = o01;
            *(float2*)(Cf + g1) = o23;
        }
    }
}

// ---------------------------------------------------------------------------
// Fused flash-style attention — ctx values bitwise identical to R5/R16.
// R17: K tile staged in registers one tile ahead; V tile via cp.async into
// smem overlapped with the S/softmax phase (pure scheduling; math unchanged).
#define AT_TQ 128
#define AT_TK 64
#define QS_LD 132
#define KS_LD 68
#define PS_LD 68

__global__ void __launch_bounds__(256, 2)
attn_fused(const float* __restrict__ Q, const float* __restrict__ K,
           const float* __restrict__ V, float* __restrict__ Ctx,
           unsigned int* __restrict__ amax1) {
    extern __shared__ float sm[];
    float* Qs = sm;
    float* Ks = Qs + 64 * QS_LD;
    float* Vs = Ks + 64 * KS_LD;
    float* Ps = Vs + 64 * KS_LD;
    __shared__ float amred[8];

    const int tid = threadIdx.x;
    const int tx = tid & 15, ty = tid >> 4;
    const int z = blockIdx.y, b = z >> 4, h = z & 15;
    const size_t bm = (size_t)blockIdx.x * AT_TQ;
    const float* Qg = Q + ((size_t)b * SS) * DD + h * HD;
    const float* Kg = K + ((size_t)b * SS) * DD + h * HD;
    const float* Vg = V + ((size_t)b * SS) * DD + h * HD;

    // per-thread K/V load coords (4 float4 each per tile)
    const int lc = tid >> 4;             // key row 0..15 base (c = lc + i*16)
    const int lq = (tid & 15) << 2;      // dim 0..60
    const uint32_t vs32 = smem_u32(Vs);

#pragma unroll
    for (int i = 0; i < 8; i++) {
        int idx = tid + i * 256;
        int r = idx >> 4;
        int q = (idx & 15) << 2;
        float4 v = *(const float4*)(Qg + (bm + r) * (size_t)DD + q);
        Qs[(q + 0) * QS_LD + r] = v.x; Qs[(q + 1) * QS_LD + r] = v.y;
        Qs[(q + 2) * QS_LD + r] = v.z; Qs[(q + 3) * QS_LD + r] = v.w;
    }

    float m_reg[8], l_reg[8];
    u64t acc2[8][2];
#pragma unroll
    for (int i = 0; i < 8; i++) {
        m_reg[i] = -1e30f; l_reg[i] = 0.0f;
        acc2[i][0] = 0ull; acc2[i][1] = 0ull;
    }

    // prologue: stage K tile 0 in registers
    float4 kbuf[4];
#pragma unroll
    for (int i = 0; i < 4; i++) {
        int c = lc + i * 16;
        kbuf[i] = *(const float4*)(Kg + (size_t)c * DD + lq);
    }

    for (int kt0 = 0; kt0 < SS; kt0 += AT_TK) {
        __syncthreads();   // prev iter done reading Ks/Vs/Ps
        // store staged K tile (transposed, same layout as before)
#pragma unroll
        for (int i = 0; i < 4; i++) {
            int c = lc + i * 16;
            Ks[(lq + 0) * KS_LD + c] = kbuf[i].x;
            Ks[(lq + 1) * KS_LD + c] = kbuf[i].y;
            Ks[(lq + 2) * KS_LD + c] = kbuf[i].z;
            Ks[(lq + 3) * KS_LD + c] = kbuf[i].w;
        }
        // V tile via cp.async (completed before the P@V barrier below)
#pragma unroll
        for (int i = 0; i < 4; i++) {
            int c = lc + i * 16;
            cp_async16(vs32 + (c * KS_LD + lq) * 4, Vg + (size_t)(kt0 + c) * DD + lq);
        }
        CP_COMMIT();
        // stage K for next tile (in flight during S/softmax)
        if (kt0 + AT_TK < SS) {
#pragma unroll
            for (int i = 0; i < 4; i++) {
                int c = lc + i * 16;
                kbuf[i] = *(const float4*)(Kg + (size_t)(kt0 + AT_TK + c) * DD + lq);
            }
        }
        __syncthreads();   // Ks visible

        u64t s2[8][2];
#pragma unroll
        for (int i = 0; i < 8; i++) { s2[i][0] = 0ull; s2[i][1] = 0ull; }
#pragma unroll 4
        for (int kk = 0; kk < 64; kk++) {
            float a[8], bb[4];
            *(float4*)&a[0] = *(const float4*)&Qs[kk * QS_LD + ty * 8];
            *(float4*)&a[4] = *(const float4*)&Qs[kk * QS_LD + ty * 8 + 4];
            *(float4*)&bb[0] = *(const float4*)&Ks[kk * KS_LD + tx * 4];
            u64t B2[2];
            B2[0] = pack2(bb[0], bb[1]); B2[1] = pack2(bb[2], bb[3]);
#pragma unroll
            for (int i = 0; i < 8; i++) {
                u64t A2 = bcast2(a[i]);
                fma2(s2[i][0], A2, B2[0]);
                fma2(s2[i][1], A2, B2[1]);
            }
        }

#pragma unroll
        for (int i = 0; i < 8; i++) {
            float s[4];
            unpack2(s2[i][0], s[0], s[1]);
            unpack2(s2[i][1], s[2], s[3]);
            float mx = fmaxf(fmaxf(s[0], s[1]), fmaxf(s[2], s[3]));
            mx *= 0.125f;
#pragma unroll
            for (int o = 8; o; o >>= 1)
                mx = fmaxf(mx, __shfl_xor_sync(0xffffffffu, mx, o));
            float mn = fmaxf(m_reg[i], mx);
            float alpha = expf(m_reg[i] - mn);
            float4 p4;
            p4.x = expf(s[0] * 0.125f - mn);
            p4.y = expf(s[1] * 0.125f - mn);
            p4.z = expf(s[2] * 0.125f - mn);
            p4.w = expf(s[3] * 0.125f - mn);
            *(float4*)&Ps[(ty * 8 + i) * PS_LD + tx * 4] = p4;
            float ps = (p4.x + p4.y) + (p4.z + p4.w);
#pragma unroll
            for (int o = 8; o; o >>= 1)
                ps += __shfl_xor_sync(0xffffffffu, ps, o);
            l_reg[i] = l_reg[i] * alpha + ps;
            m_reg[i] = mn;
            u64t al2 = bcast2(alpha);
            mul2(acc2[i][0], al2);
            mul2(acc2[i][1], al2);
        }
        CP_WAIT0();        // V tile landed
        __syncthreads();   // Ps + Vs visible

#pragma unroll 4
        for (int kt = 0; kt < 64; kt++) {
            float a[8], bb[4];
#pragma unroll
            for (int i = 0; i < 8; i++) a[i] = Ps[(ty * 8 + i) * PS_LD + kt];
            *(float4*)&bb[0] = *(const float4*)&Vs[kt * KS_LD + tx * 4];
            u64t B2[2];
            B2[0] = pack2(bb[0], bb[1]); B2[1] = pack2(bb[2], bb[3]);
#pragma unroll
            for (int i = 0; i < 8; i++) {
                u64t A2 = bcast2(a[i]);
                fma2(acc2[i][0], A2, B2[0]);
                fma2(acc2[i][1], A2, B2[1]);
            }
        }
    }

    float* Cg = Ctx + ((size_t)b * SS) * DD + h * HD;
    float lmax = 0.0f;
#pragma unroll
    for (int i = 0; i < 8; i++) {
        float inv = __fdiv_rn(1.0f, l_reg[i]);
        float4 v;
        unpack2(acc2[i][0], v.x, v.y);
        unpack2(acc2[i][1], v.z, v.w);
        v.x *= inv; v.y *= inv; v.z *= inv; v.w *= inv;
        lmax = fmaxf(lmax, fmaxf(fmaxf(fabsf(v.x), fabsf(v.y)),
                                 fmaxf(fabsf(v.z), fabsf(v.w))));
        *(float4*)(Cg + (bm + ty * 8 + i) * (size_t)DD + tx * 4) = v;
    }
#pragma unroll
    for (int o = 16; o; o >>= 1)
        lmax = fmaxf(lmax, __shfl_xor_sync(0xffffffffu, lmax, o));
    if ((tid & 31) == 0) amred[tid >> 5] = lmax;
    __syncthreads();
    if (tid == 0) {
        float mm = amred[0];
#pragma unroll
        for (int w = 1; w < 8; w++) mm = fmaxf(mm, amred[w]);
        atomicMax(amax1, __float_as_uint(mm));
    }
}

// ---------------------------------------------------------------------------
// t = qdq(X+Y, s[sa]); Out = qdq(layernorm(t)*w+b, s[sl]).  Bitwise R5 path.
__global__ void __launch_bounds__(256)
add_ln(const float* __restrict__ X, const float* __restrict__ Y,
       const float* __restrict__ w, const float* __restrict__ bvec,
       const float* __restrict__ opsc, int sa, int sl,
       float* __restrict__ Out) {
    __shared__ float red[8];
    const int tid = threadIdx.x;
    const size_t base = (size_t)blockIdx.x * 1024;
    const float s_add = opsc[sa] * 0.05f;
    const float s_ln  = opsc[sl] * 0.05f;
    const int c = tid * 4;
    float4 xv = *(const float4*)(X + base + c);
    float4 yv = *(const float4*)(Y + base + c);
    float v0 = qdqf(xv.x + yv.x, s_add);
    float v1 = qdqf(xv.y + yv.y, s_add);
    float v2 = qdqf(xv.z + yv.z, s_add);
    float v3 = qdqf(xv.w + yv.w, s_add);

    float lsum = (v0 + v1) + (v2 + v3);
#pragma unroll
    for (int o = 16; o; o >>= 1) lsum += __shfl_xor_sync(0xffffffffu, lsum, o);
    if ((tid & 31) == 0) red[tid >> 5] = lsum;
    __syncthreads();
    float tot = 0.0f;
#pragma unroll
    for (int ww = 0; ww < 8; ww++) tot += red[ww];
    float mu = tot * (1.0f / 1024.0f);

    float d0 = v0 - mu, d1 = v1 - mu, d2 = v2 - mu, d3 = v3 - mu;
    float lv = d0 * d0 + d1 * d1 + d2 * d2 + d3 * d3;
#pragma unroll
    for (int o = 16; o; o >>= 1) lv += __shfl_xor_sync(0xffffffffu, lv, o);
    __syncthreads();
    if ((tid & 31) == 0) red[tid >> 5] = lv;
    __syncthreads();
    float vtot = 0.0f;
#pragma unroll
    for (int ww = 0; ww < 8; ww++) vtot += red[ww];
    float var = vtot * (1.0f / 1024.0f);
    float rstd = __fdiv_rn(1.0f, __fsqrt_rn(var + 1e-5f));

    float4 w4 = *(const float4*)(w + c);
    float4 b4 = *(const float4*)(bvec + c);
    float4 o4;
    o4.x = qdqf(d0 * rstd * w4.x + b4.x, s_ln);
    o4.y = qdqf(d1 * rstd * w4.y + b4.y, s_ln);
    o4.z = qdqf(d2 * rstd * w4.z + b4.z, s_ln);
    o4.w = qdqf(d3 * rstd * w4.w + b4.w, s_ln);
    *(float4*)(Out + base + c) = o4;
}

// ---------------------------------------------------------------------------
extern "C" void kernel_launch(void* const* d_in, const int* in_sizes, int n_in,
                              void* d_out, int out_size) {
    const float* x    = (const float*)d_in[0];
    const float* wq   = (const float*)d_in[2];
    const float* bq   = (const float*)d_in[3];
    const float* wk   = (const float*)d_in[4];
    const float* bk   = (const float*)d_in[5];
    const float* wv   = (const float*)d_in[6];
    const float* bv   = (const float*)d_in[7];
    const float* wo   = (const float*)d_in[8];
    const float* bo   = (const float*)d_in[9];
    const float* w1   = (const float*)d_in[10];
    const float* b1   = (const float*)d_in[11];
    const float* w2   = (const float*)d_in[12];
    const float* b2   = (const float*)d_in[13];
    const float* ln1w = (const float*)d_in[14];
    const float* ln1b = (const float*)d_in[15];
    const float* ln2w = (const float*)d_in[16];
    const float* ln2b = (const float*)d_in[17];
    const float* opsc = (const float*)d_in[18];
    float* out = (float*)d_out;

    float *xq, *q, *k, *v, *ctx, *o, *h, *f2;
    unsigned char *fu, *ctxu;
    signed char *w24, *wo4;
    float *cs2, *cso;
    unsigned int* amax;
    cudaGetSymbolAddress((void**)&xq,  g_xq);
    cudaGetSymbolAddress((void**)&q,   g_q);
    cudaGetSymbolAddress((void**)&k,   g_k);
    cudaGetSymbolAddress((void**)&v,   g_v);
    cudaGetSymbolAddress((void**)&ctx, g_ctx);
    cudaGetSymbolAddress((void**)&o,   g_o);
    cudaGetSymbolAddress((void**)&h,   g_h);
    cudaGetSymbolAddress((void**)&f2,  g_f2);
    cudaGetSymbolAddress((void**)&fu,  g_fu);
    cudaGetSymbolAddress((void**)&ctxu, g_ctxu);
    cudaGetSymbolAddress((void**)&w24, g_w24);
    cudaGetSymbolAddress((void**)&wo4, g_wo4);
    cudaGetSymbolAddress((void**)&cs2, g_cs2);
    cudaGetSymbolAddress((void**)&cso, g_cso);
    cudaGetSymbolAddress((void**)&amax, g_amax);

    static const int ATT_SMEM = (64 * QS_LD + 64 * KS_LD + 64 * KS_LD + 128 * PS_LD) * 4;
    cudaFuncSetAttribute(attn_fused, cudaFuncAttributeMaxDynamicSharedMemorySize, ATT_SMEM);
    cudaFuncSetAttribute(gemm_imma, cudaFuncAttributeMaxDynamicSharedMemorySize, G8_TOTAL);

    init_amax_kernel<<<1, 32>>>();
    absmax_kernel<<<1024, 256>>>(x, NX / 4, amax + 0);
    absmax_kernel<<<256, 256>>>(wo, 262144, amax + 5);
    absmax_kernel<<<512, 256>>>(w2, 1048576, amax + 7);

    // O + FFN2 weight integer splits + zero-point row sums
    split_w8_kernel<<<2048, 256>>>(wo, wo4, 1048576, amax + 5);
    split_w8_kernel<<<4096, 256>>>(w2, w24, 4194304, amax + 7);
    rowsum_kernel<<<1024, 256>>>(wo4, 1024, 1024, amax + 5, cso);
    rowsum_kernel<<<1024, 256>>>(w24, 1024, 4096, amax + 7, cs2);

    // input quantization (R5 path, fp32 qdq values)
    qdq_x_kernel<<<2048, 256>>>(x, xq, amax + 0, NX / 4);

    // QKV projections on the R5 f32x2 GEMM (reference wiring: k<-wv, v<-wk)
    dim3 g64(8, 64);
    gemm_tn<<<g64, 256>>>(xq, wq, q, DD, DD, DD, DD, bq, opsc, 0, 0, nullptr);
    gemm_tn<<<g64, 256>>>(xq, wv, k, DD, DD, DD, DD, bv, opsc, 1, 0, nullptr);
    gemm_tn<<<g64, 256>>>(xq, wk, v, DD, DD, DD, DD, bk, opsc, 2, 0, nullptr);

    // fused attention (+ fused ctx abs-max into amax[1]); ctx bitwise R16
    attn_fused<<<dim3(SS / AT_TQ, BB * HH), 256, ATT_SMEM>>>(q, k, v, ctx, amax + 1);

    // ctx codes (dynamic scale); O projection on IMMA (banked R16)
    qdq_codes_kernel<<<2048, 256>>>(ctx, ctxu, amax + 1, NX / 4);
    gemm_imma<<<dim3(8, 64), 256, G8_TOTAL>>>(ctxu, wo4, 1024, 1024, bo, cso,
                                              amax + 1, amax + 5, opsc, 0, 3, 0, o);

    // residual + LN1 (bitwise R5)
    add_ln<<<BB * SS, 256>>>(xq, o, ln1w, ln1b, opsc, 8, 6, h);

    // FFN1 on R5 GEMM — u8 codes only (fp32 store dropped; f unused)
    gemm_tn<<<dim3(32, 64), 256>>>(h, w1, nullptr, DD, DD, FF, DD, b1, opsc, 4, 1, fu);

    // FFN2 on IMMA (banked R15 config)
    gemm_imma<<<dim3(8, 64), 256, G8_TOTAL>>>(fu, w24, 1024, 4096, b2, cs2,
                                              nullptr, amax + 7, opsc, 4, 5, 0, f2);

    // residual + LN2 -> output
    add_ln<<<BB * SS, 256>>>(h, f2, ln2w, ln2b, opsc, 9, 7, out);
}